// round 3
// baseline (speedup 1.0000x reference)
#include <cuda_runtime.h>
#include <math.h>

#define NB 2
#define NCH 512
#define NSP 4096
#define NGROUPS 32
#define GELEMS 65536          // (NCH/NGROUPS) * NSP = 16*4096
#define BCH_N ((size_t)NCH * NSP)      // per-batch [c,n] stride
#define ATT_N ((size_t)NSP * NSP)      // per-batch [n,n] stride

// ---------------- scratch (static device globals; no allocations) ------------
__device__ float g_h[NB * NCH * NSP];       // group-normed activations
__device__ float g_q[NB * NCH * NSP];
__device__ float g_k[NB * NCH * NSP];
__device__ float g_v[NB * NCH * NSP];
__device__ float g_o[NB * NCH * NSP];
__device__ float g_attn[(size_t)NB * NSP * NSP];   // 134 MB
__device__ float g_stats[NB * NGROUPS * 2];        // mean, rstd per (b,g)

// ---------------- GroupNorm: stats ------------------------------------------
__global__ void gn_stats_kernel(const float* __restrict__ x) {
    __shared__ float sh_s[256];
    __shared__ float sh_ss[256];
    const int bg = blockIdx.x;                      // b*32 + g (groups contiguous)
    const float* p = x + (size_t)bg * GELEMS;
    float s = 0.f, ss = 0.f;
    for (int i = threadIdx.x * 4; i < GELEMS; i += 256 * 4) {
        float4 v = *(const float4*)&p[i];
        s  += v.x + v.y + v.z + v.w;
        ss += v.x * v.x + v.y * v.y + v.z * v.z + v.w * v.w;
    }
    sh_s[threadIdx.x] = s;
    sh_ss[threadIdx.x] = ss;
    __syncthreads();
    for (int st = 128; st > 0; st >>= 1) {
        if (threadIdx.x < st) {
            sh_s[threadIdx.x]  += sh_s[threadIdx.x + st];
            sh_ss[threadIdx.x] += sh_ss[threadIdx.x + st];
        }
        __syncthreads();
    }
    if (threadIdx.x == 0) {
        float mean = sh_s[0] * (1.f / GELEMS);
        float var  = sh_ss[0] * (1.f / GELEMS) - mean * mean;
        g_stats[bg * 2 + 0] = mean;
        g_stats[bg * 2 + 1] = rsqrtf(var + 1e-6f);
    }
}

// ---------------- GroupNorm: normalize --------------------------------------
__global__ void gn_norm_kernel(const float* __restrict__ x,
                               const float* __restrict__ gamma,
                               const float* __restrict__ beta) {
    int i4 = blockIdx.x * blockDim.x + threadIdx.x;   // one float4 each
    size_t e = (size_t)i4 * 4;
    int bg = (int)(e >> 16);                          // / 65536
    int c  = (int)((e >> 12) & (NCH - 1));            // (e/4096) % 512
    float mean = g_stats[bg * 2 + 0];
    float rstd = g_stats[bg * 2 + 1];
    float ga = gamma[c] * rstd;
    float be = beta[c] - mean * ga;
    float4 xv = *(const float4*)&x[e];
    float4 hv;
    hv.x = xv.x * ga + be;
    hv.y = xv.y * ga + be;
    hv.z = xv.z * ga + be;
    hv.w = xv.w * ga + be;
    *(float4*)&g_h[e] = hv;
}

// ---------------- generic 128x128x8 register-tiled SGEMM ---------------------
// C[m,n] = alpha * sum_k A(m,k)*B(k,n)  [+ bias[m]] [+ resid[m*ldc+n]]
// transA: A(m,k) = A[k*lda + m]  else A[m*lda + k]
// transB: B(k,n) = B[n*ldb + k]  else B[k*ldb + n]
// grid: (N/128, M/128, batch); 256 threads. All dims assumed multiples of 128/8.
__global__ void __launch_bounds__(256)
sgemm_kernel(const float* __restrict__ A, const float* __restrict__ B,
             const float* __restrict__ bias, const float* __restrict__ resid,
             float* __restrict__ C,
             int M, int N, int K, int lda, int ldb, int ldc,
             long long sA, long long sB, long long sC,
             float alpha, int transA, int transB) {
    const int bz = blockIdx.z;
    A += (size_t)bz * sA;
    B += (size_t)bz * sB;
    C += (size_t)bz * sC;
    if (resid) resid += (size_t)bz * sC;

    __shared__ float As[8][128];
    __shared__ float Bs[8][128];

    const int bm = blockIdx.y * 128;
    const int bn = blockIdx.x * 128;
    const int tid = threadIdx.x;
    const int tm = (tid / 16) * 8;
    const int tn = (tid % 16) * 8;

    float acc[8][8];
#pragma unroll
    for (int i = 0; i < 8; i++)
#pragma unroll
        for (int j = 0; j < 8; j++) acc[i][j] = 0.f;

    for (int k0 = 0; k0 < K; k0 += 8) {
        // ---- load A tile into As[k][m] ----
        if (!transA) {
            int m = tid >> 1, kq = (tid & 1) * 4;
            float4 a = *(const float4*)&A[(size_t)(bm + m) * lda + k0 + kq];
            As[kq + 0][m] = a.x;
            As[kq + 1][m] = a.y;
            As[kq + 2][m] = a.z;
            As[kq + 3][m] = a.w;
        } else {
            int k = tid >> 5, mq = (tid & 31) * 4;
            float4 a = *(const float4*)&A[(size_t)(k0 + k) * lda + bm + mq];
            *(float4*)&As[k][mq] = a;
        }
        // ---- load B tile into Bs[k][n] ----
        if (!transB) {
            int k = tid >> 5, nq = (tid & 31) * 4;
            float4 b = *(const float4*)&B[(size_t)(k0 + k) * ldb + bn + nq];
            *(float4*)&Bs[k][nq] = b;
        } else {
            int n = tid >> 1, kq = (tid & 1) * 4;
            float4 b = *(const float4*)&B[(size_t)(bn + n) * ldb + k0 + kq];
            Bs[kq + 0][n] = b.x;
            Bs[kq + 1][n] = b.y;
            Bs[kq + 2][n] = b.z;
            Bs[kq + 3][n] = b.w;
        }
        __syncthreads();

#pragma unroll
        for (int k = 0; k < 8; k++) {
            float a[8], b[8];
#pragma unroll
            for (int i = 0; i < 8; i++) a[i] = As[k][tm + i];
#pragma unroll
            for (int j = 0; j < 8; j++) b[j] = Bs[k][tn + j];
#pragma unroll
            for (int i = 0; i < 8; i++)
#pragma unroll
                for (int j = 0; j < 8; j++) acc[i][j] += a[i] * b[j];
        }
        __syncthreads();
    }

    // ---- epilogue ----
#pragma unroll
    for (int i = 0; i < 8; i++) {
        int m = bm + tm + i;
        float bi = bias ? bias[m] : 0.f;
#pragma unroll
        for (int jq = 0; jq < 8; jq += 4) {
            size_t off = (size_t)m * ldc + bn + tn + jq;
            float4 r;
            r.x = acc[i][jq + 0] * alpha + bi;
            r.y = acc[i][jq + 1] * alpha + bi;
            r.z = acc[i][jq + 2] * alpha + bi;
            r.w = acc[i][jq + 3] * alpha + bi;
            if (resid) {
                float4 rv = *(const float4*)&resid[off];
                r.x += rv.x; r.y += rv.y; r.z += rv.z; r.w += rv.w;
            }
            *(float4*)&C[off] = r;
        }
    }
}

// ---------------- row softmax (row cached in smem; 1 read + 1 write) --------
__global__ void softmax_kernel(float* __restrict__ attn) {
    __shared__ float row[NSP];       // 16 KB
    __shared__ float red[256];
    const size_t r = blockIdx.x;
    float* p = attn + r * NSP;
    const int tid = threadIdx.x;

    float m = -1e30f;
    for (int i = tid; i < NSP; i += 256) {
        float v = p[i];
        row[i] = v;
        m = fmaxf(m, v);
    }
    red[tid] = m;
    __syncthreads();
    for (int st = 128; st > 0; st >>= 1) {
        if (tid < st) red[tid] = fmaxf(red[tid], red[tid + st]);
        __syncthreads();
    }
    m = red[0];
    __syncthreads();

    float s = 0.f;
    for (int i = tid; i < NSP; i += 256) {
        float e = __expf(row[i] - m);
        row[i] = e;
        s += e;
    }
    red[tid] = s;
    __syncthreads();
    for (int st = 128; st > 0; st >>= 1) {
        if (tid < st) red[tid] += red[tid + st];
        __syncthreads();
    }
    float inv = 1.f / red[0];
    for (int i = tid; i < NSP; i += 256) p[i] = row[i] * inv;
}

// ---------------- launch -----------------------------------------------------
extern "C" void kernel_launch(void* const* d_in, const int* in_sizes, int n_in,
                              void* d_out, int out_size) {
    const float* x     = (const float*)d_in[0];
    const float* gamma = (const float*)d_in[1];
    const float* beta  = (const float*)d_in[2];
    const float* wq    = (const float*)d_in[3];
    const float* bq    = (const float*)d_in[4];
    const float* wk    = (const float*)d_in[5];
    const float* bk    = (const float*)d_in[6];
    const float* wv    = (const float*)d_in[7];
    const float* bv    = (const float*)d_in[8];
    const float* wo    = (const float*)d_in[9];
    const float* bo    = (const float*)d_in[10];
    float* out = (float*)d_out;

    float *h = nullptr, *q = nullptr, *k = nullptr, *v = nullptr,
          *o = nullptr, *attn = nullptr;
    cudaGetSymbolAddress((void**)&h, g_h);
    cudaGetSymbolAddress((void**)&q, g_q);
    cudaGetSymbolAddress((void**)&k, g_k);
    cudaGetSymbolAddress((void**)&v, g_v);
    cudaGetSymbolAddress((void**)&o, g_o);
    cudaGetSymbolAddress((void**)&attn, g_attn);

    const float scale = 0.044194173824159216f;   // 512^-0.5

    // 1) GroupNorm
    gn_stats_kernel<<<NB * NGROUPS, 256>>>(x);
    gn_norm_kernel<<<(NB * NCH * NSP) / (4 * 256), 256>>>(x, gamma, beta);

    // 2) Q, K, V projections: [512,512] @ [512,4096] per batch
    dim3 gProj(NSP / 128, NCH / 128, NB);
    sgemm_kernel<<<gProj, 256>>>(wq, h, bq, nullptr, q,
                                 NCH, NSP, NCH, NCH, NSP, NSP,
                                 0, (long long)BCH_N, (long long)BCH_N,
                                 1.f, 0, 0);
    sgemm_kernel<<<gProj, 256>>>(wk, h, bk, nullptr, k,
                                 NCH, NSP, NCH, NCH, NSP, NSP,
                                 0, (long long)BCH_N, (long long)BCH_N,
                                 1.f, 0, 0);
    sgemm_kernel<<<gProj, 256>>>(wv, h, bv, nullptr, v,
                                 NCH, NSP, NCH, NCH, NSP, NSP,
                                 0, (long long)BCH_N, (long long)BCH_N,
                                 1.f, 0, 0);

    // 3) S = scale * Q^T K : [4096,4096] per batch  (A = Q transposed view)
    dim3 gS(NSP / 128, NSP / 128, NB);
    sgemm_kernel<<<gS, 256>>>(q, k, nullptr, nullptr, attn,
                              NSP, NSP, NCH, NSP, NSP, NSP,
                              (long long)BCH_N, (long long)BCH_N, (long long)ATT_N,
                              scale, 1, 0);

    // 4) row softmax over j
    softmax_kernel<<<NB * NSP, 256>>>(attn);

    // 5) O[c,i] = sum_j V[c,j] * attn[i,j]   (B = attn, transB)
    dim3 gO(NSP / 128, NCH / 128, NB);
    sgemm_kernel<<<gO, 256>>>(v, attn, nullptr, nullptr, o,
                              NCH, NSP, NSP, NSP, NSP, NSP,
                              (long long)BCH_N, (long long)ATT_N, (long long)BCH_N,
                              1.f, 0, 1);

    // 6) out = x + wo @ o + bo
    sgemm_kernel<<<gO, 256>>>(wo, o, bo, x, out,
                              NCH, NSP, NCH, NCH, NSP, NSP,
                              0, (long long)BCH_N, (long long)BCH_N,
                              1.f, 0, 0);
}

// round 5
// speedup vs baseline: 2.3923x; 2.3923x over previous
#include <cuda_runtime.h>
#include <cuda_bf16.h>
#include <math.h>
#include <stdint.h>

#define NB 2
#define NCH 512
#define NSP 4096
#define NGROUPS 32
#define GELEMS 65536                       // 16 * 4096 per (b,g)
#define BCH_N ((size_t)NCH * NSP)          // 2097152
#define ATT_N ((size_t)NSP * NSP)          // 16777216

// ---------------- scratch (static device globals; no allocations) ------------
__device__ __nv_bfloat16 g_hT_hi[NB * NSP * NCH];   // [b][n][c]
__device__ __nv_bfloat16 g_hT_lo[NB * NSP * NCH];
__device__ __nv_bfloat16 g_w_hi[4][NCH * NCH];      // wq, wk, wv, wo
__device__ __nv_bfloat16 g_w_lo[4][NCH * NCH];
__device__ __nv_bfloat16 g_qT_hi[NB * NSP * NCH];   // [b][n][c]
__device__ __nv_bfloat16 g_qT_lo[NB * NSP * NCH];
__device__ __nv_bfloat16 g_kT_hi[NB * NSP * NCH];
__device__ __nv_bfloat16 g_kT_lo[NB * NSP * NCH];
__device__ __nv_bfloat16 g_v_hi[NB * NCH * NSP];    // [b][c][n]
__device__ __nv_bfloat16 g_v_lo[NB * NCH * NSP];
__device__ float         g_S[(size_t)NB * NSP * NSP];       // 134 MB
__device__ __nv_bfloat16 g_attn_hi[(size_t)NB * NSP * NSP]; // [b][i][j]
__device__ __nv_bfloat16 g_attn_lo[(size_t)NB * NSP * NSP];
__device__ __nv_bfloat16 g_oT_hi[NB * NSP * NCH];   // [b][i][c]
__device__ __nv_bfloat16 g_oT_lo[NB * NSP * NCH];
__device__ float         g_stats[NB * NGROUPS * 2];

// ---------------- PTX helpers ------------------------------------------------
__device__ __forceinline__ uint32_t smem_u32(const void* p) {
    uint32_t a;
    asm("{ .reg .u64 t; cvta.to.shared.u64 t, %1; cvt.u32.u64 %0, t; }" : "=r"(a) : "l"(p));
    return a;
}
__device__ __forceinline__ void cpa16(uint32_t dst, const void* src) {
    asm volatile("cp.async.cg.shared.global [%0], [%1], 16;" :: "r"(dst), "l"(src));
}
#define CP_COMMIT() asm volatile("cp.async.commit_group;")
#define CP_WAIT(n)  asm volatile("cp.async.wait_group %0;" :: "n"(n) : "memory")

#define LDSM4(r, a) \
    asm volatile("ldmatrix.sync.aligned.m8n8.x4.shared.b16 {%0,%1,%2,%3}, [%4];" \
        : "=r"((r)[0]), "=r"((r)[1]), "=r"((r)[2]), "=r"((r)[3]) : "r"(a))
#define LDSM2(r, a) \
    asm volatile("ldmatrix.sync.aligned.m8n8.x2.shared.b16 {%0,%1}, [%2];" \
        : "=r"((r)[0]), "=r"((r)[1]) : "r"(a))
#define MMA_BF16(d, a, b) \
    asm volatile("mma.sync.aligned.m16n8k16.row.col.f32.bf16.bf16.f32 " \
        "{%0,%1,%2,%3}, {%4,%5,%6,%7}, {%8,%9}, {%0,%1,%2,%3};" \
        : "+f"((d)[0]), "+f"((d)[1]), "+f"((d)[2]), "+f"((d)[3]) \
        : "r"((a)[0]), "r"((a)[1]), "r"((a)[2]), "r"((a)[3]), \
          "r"((b)[0]), "r"((b)[1]))

// ---------------- GroupNorm stats --------------------------------------------
__global__ void gn_stats_kernel(const float* __restrict__ x) {
    __shared__ float sh_s[256], sh_ss[256];
    const int bg = blockIdx.x;
    const float* p = x + (size_t)bg * GELEMS;
    float s = 0.f, ss = 0.f;
    for (int i = threadIdx.x * 4; i < GELEMS; i += 256 * 4) {
        float4 v = *(const float4*)&p[i];
        s  += v.x + v.y + v.z + v.w;
        ss += v.x * v.x + v.y * v.y + v.z * v.z + v.w * v.w;
    }
    sh_s[threadIdx.x] = s; sh_ss[threadIdx.x] = ss;
    __syncthreads();
    for (int st = 128; st > 0; st >>= 1) {
        if (threadIdx.x < st) {
            sh_s[threadIdx.x]  += sh_s[threadIdx.x + st];
            sh_ss[threadIdx.x] += sh_ss[threadIdx.x + st];
        }
        __syncthreads();
    }
    if (threadIdx.x == 0) {
        float mean = sh_s[0] * (1.f / GELEMS);
        float var  = sh_ss[0] * (1.f / GELEMS) - mean * mean;
        g_stats[bg * 2 + 0] = mean;
        g_stats[bg * 2 + 1] = rsqrtf(var + 1e-6f);
    }
}

// ------------- GroupNorm + transpose + bf16 hi/lo split ----------------------
// x [b][c][n] fp32  ->  hT [b][n][c] bf16 hi/lo
__global__ void gn_tr_split_kernel(const float* __restrict__ x,
                                   const float* __restrict__ gamma,
                                   const float* __restrict__ beta) {
    __shared__ float t[32][33];
    const int b  = blockIdx.z;
    const int c0 = blockIdx.y * 32;
    const int n0 = blockIdx.x * 32;
    const float* xb = x + (size_t)b * BCH_N;
    const int tx = threadIdx.x, ty = threadIdx.y;
#pragma unroll
    for (int r = 0; r < 4; r++) {
        int c = c0 + ty + r * 8;
        int bg = b * NGROUPS + (c >> 4);
        float mean = g_stats[bg * 2 + 0], rstd = g_stats[bg * 2 + 1];
        float ga = gamma[c] * rstd;
        float be = beta[c] - mean * ga;
        t[ty + r * 8][tx] = xb[(size_t)c * NSP + n0 + tx] * ga + be;
    }
    __syncthreads();
#pragma unroll
    for (int r = 0; r < 4; r++) {
        int n = n0 + ty + r * 8;
        int c = c0 + tx;
        float v = t[tx][ty + r * 8];
        __nv_bfloat16 h = __float2bfloat16(v);
        size_t off = ((size_t)b * NSP + n) * NCH + c;
        g_hT_hi[off] = h;
        g_hT_lo[off] = __float2bfloat16(v - __bfloat162float(h));
    }
}

// ---------------- fp32 -> bf16 hi/lo split (weights) -------------------------
__global__ void split_kernel(const float* __restrict__ src,
                             __nv_bfloat16* __restrict__ hi,
                             __nv_bfloat16* __restrict__ lo, int n) {
    int i = blockIdx.x * blockDim.x + threadIdx.x;
    if (i < n) {
        float v = src[i];
        __nv_bfloat16 h = __float2bfloat16(v);
        hi[i] = h;
        lo[i] = __float2bfloat16(v - __bfloat162float(h));
    }
}

// ---------------- softmax row -> bf16 hi/lo split ----------------------------
__global__ void softmax_split_kernel(const float* __restrict__ S) {
    __shared__ float row[NSP];
    __shared__ float red[256];
    const size_t r = blockIdx.x;
    const float* p = S + r * NSP;
    const int tid = threadIdx.x;

    float m = -1e30f;
    for (int i = tid; i < NSP; i += 256) {
        float v = p[i];
        row[i] = v;
        m = fmaxf(m, v);
    }
    red[tid] = m; __syncthreads();
    for (int st = 128; st > 0; st >>= 1) {
        if (tid < st) red[tid] = fmaxf(red[tid], red[tid + st]);
        __syncthreads();
    }
    m = red[0]; __syncthreads();

    float s = 0.f;
    for (int i = tid; i < NSP; i += 256) {
        float e = __expf(row[i] - m);
        row[i] = e;
        s += e;
    }
    red[tid] = s; __syncthreads();
    for (int st = 128; st > 0; st >>= 1) {
        if (tid < st) red[tid] += red[tid + st];
        __syncthreads();
    }
    float inv = 1.f / red[0];
    size_t base = r * NSP;
    for (int i = tid; i < NSP; i += 256) {
        float v = row[i] * inv;
        __nv_bfloat16 h = __float2bfloat16(v);
        g_attn_hi[base + i] = h;
        g_attn_lo[base + i] = __float2bfloat16(v - __bfloat162float(h));
    }
}

// ---------------- bf16x3-split GEMM via mma.sync (HMMA) ----------------------
// C[M,N] = alpha * A[M,K] . B[N,K]^T  (+ bias) (+ resid), A=Ah+Al, B=Bh+Bl
// CTA tile 128x128x32, 8 warps (2x4), warp tile 64x32, cp.async double buffer.
// SMEM rows padded to 80B (64B data + 16B) -> conflict-free ldmatrix.
#define ROWB 80
#define T_A_HI 0
#define T_A_LO 10240
#define T_B_HI 20480
#define T_B_LO 30720
#define STAGE  40960
#define SMEM_GEMM (2 * STAGE)     // 81920

__global__ void __launch_bounds__(256, 1)
gemm_mma(const __nv_bfloat16* __restrict__ Ah, const __nv_bfloat16* __restrict__ Al,
         long long sA, int lda,
         const __nv_bfloat16* __restrict__ Bh, const __nv_bfloat16* __restrict__ Bl,
         long long sB, int ldb,
         float* __restrict__ Cf,
         __nv_bfloat16* __restrict__ Chi, __nv_bfloat16* __restrict__ Clo,
         long long sC, int ldc,
         const float* __restrict__ bias, int bias_mode,
         const float* __restrict__ resid, float alpha, int K) {
    extern __shared__ char smem[];
    const uint32_t sb = smem_u32(smem);
    const int tid = threadIdx.x;
    const int wid = tid >> 5, lane = tid & 31;
    const int wm = wid >> 2, wn = wid & 3;        // 2 x 4 warp grid
    const int bz = blockIdx.z;
    Ah += (size_t)bz * sA; Al += (size_t)bz * sA;
    Bh += (size_t)bz * sB; Bl += (size_t)bz * sB;
    const size_t cOff = (size_t)bz * sC;
    const int m0 = blockIdx.y * 128;
    const int n0 = blockIdx.x * 128;

    float acc[4][4][4];
#pragma unroll
    for (int i = 0; i < 4; i++)
#pragma unroll
        for (int j = 0; j < 4; j++)
#pragma unroll
            for (int r = 0; r < 4; r++) acc[i][j][r] = 0.f;

    const int nch = K / 32;

    // ---- stage loader: 128 rows x 2 tensors each for A and B ----
    const int lrow = tid >> 2;            // 0..63
    const int lu   = tid & 3;             // 16B chunk within 64B row
    {
        // prologue: stage 0
        const uint32_t stg = sb;
#pragma unroll
        for (int i = 0; i < 2; i++) {
            int row = lrow + i * 64;
            uint32_t so = row * ROWB + lu * 16;
            size_t ga = (size_t)(m0 + row) * lda + lu * 8;
            cpa16(stg + T_A_HI + so, Ah + ga);
            cpa16(stg + T_A_LO + so, Al + ga);
            size_t gb = (size_t)(n0 + row) * ldb + lu * 8;
            cpa16(stg + T_B_HI + so, Bh + gb);
            cpa16(stg + T_B_LO + so, Bl + gb);
        }
        CP_COMMIT();
    }

    for (int c = 0; c < nch; c++) {
        if (c + 1 < nch) {
            const uint32_t stg = sb + ((c + 1) & 1) * STAGE;
            const int k0 = (c + 1) * 32;
#pragma unroll
            for (int i = 0; i < 2; i++) {
                int row = lrow + i * 64;
                uint32_t so = row * ROWB + lu * 16;
                size_t ga = (size_t)(m0 + row) * lda + k0 + lu * 8;
                cpa16(stg + T_A_HI + so, Ah + ga);
                cpa16(stg + T_A_LO + so, Al + ga);
                size_t gb = (size_t)(n0 + row) * ldb + k0 + lu * 8;
                cpa16(stg + T_B_HI + so, Bh + gb);
                cpa16(stg + T_B_LO + so, Bl + gb);
            }
            CP_COMMIT();
            CP_WAIT(1);
        } else {
            CP_WAIT(0);
        }
        __syncthreads();

        const uint32_t stg = sb + (c & 1) * STAGE;
        const int lr = lane & 15, lc = lane >> 4;
        const int lt = lane & 15;
        const int br = lt & 7, bh2 = lt >> 3;
#pragma unroll
        for (int kk = 0; kk < 2; kk++) {
            uint32_t ah[4][4], alo[4][4], bhf[4][2], blf[4][2];
#pragma unroll
            for (int mi = 0; mi < 4; mi++) {
                uint32_t a = stg + T_A_HI + (uint32_t)(wm * 64 + mi * 16 + lr) * ROWB
                           + lc * 16 + kk * 32;
                LDSM4(ah[mi], a);
                LDSM4(alo[mi], a + (T_A_LO - T_A_HI));
            }
#pragma unroll
            for (int ni = 0; ni < 4; ni++) {
                uint32_t b = stg + T_B_HI + (uint32_t)(wn * 32 + ni * 8 + br) * ROWB
                           + bh2 * 16 + kk * 32;
                LDSM2(bhf[ni], b);
                LDSM2(blf[ni], b + (T_B_LO - T_B_HI));
            }
#pragma unroll
            for (int mi = 0; mi < 4; mi++)
#pragma unroll
                for (int ni = 0; ni < 4; ni++) {
                    MMA_BF16(acc[mi][ni], ah[mi], bhf[ni]);
                    MMA_BF16(acc[mi][ni], ah[mi], blf[ni]);
                    MMA_BF16(acc[mi][ni], alo[mi], bhf[ni]);
                }
        }
        __syncthreads();
    }

    // ---- epilogue ----
    const int r = lane >> 2;
    const int cb = 2 * (lane & 3);
#pragma unroll
    for (int mi = 0; mi < 4; mi++) {
#pragma unroll
        for (int h = 0; h < 2; h++) {
            const int m = m0 + wm * 64 + mi * 16 + h * 8 + r;
            const float bm = (bias_mode == 1) ? bias[m] : 0.f;
#pragma unroll
            for (int ni = 0; ni < 4; ni++) {
                const int n = n0 + wn * 32 + ni * 8 + cb;
                float v0 = acc[mi][ni][h * 2 + 0] * alpha + bm;
                float v1 = acc[mi][ni][h * 2 + 1] * alpha + bm;
                if (bias_mode == 2) { v0 += bias[n]; v1 += bias[n + 1]; }
                const size_t off = cOff + (size_t)m * ldc + n;
                if (Cf) {
                    if (resid) { v0 += resid[off]; v1 += resid[off + 1]; }
                    float2 o; o.x = v0; o.y = v1;
                    *(float2*)(Cf + off) = o;
                } else {
                    __nv_bfloat16 h0 = __float2bfloat16(v0);
                    __nv_bfloat16 h1 = __float2bfloat16(v1);
                    __nv_bfloat162 ph; ph.x = h0; ph.y = h1;
                    *(__nv_bfloat162*)(Chi + off) = ph;
                    __nv_bfloat162 pl;
                    pl.x = __float2bfloat16(v0 - __bfloat162float(h0));
                    pl.y = __float2bfloat16(v1 - __bfloat162float(h1));
                    *(__nv_bfloat162*)(Clo + off) = pl;
                }
            }
        }
    }
}

// ---------------- launch -----------------------------------------------------
extern "C" void kernel_launch(void* const* d_in, const int* in_sizes, int n_in,
                              void* d_out, int out_size) {
    const float* x     = (const float*)d_in[0];
    const float* gamma = (const float*)d_in[1];
    const float* beta  = (const float*)d_in[2];
    const float* wq    = (const float*)d_in[3];
    const float* bq    = (const float*)d_in[4];
    const float* wk    = (const float*)d_in[5];
    const float* bk    = (const float*)d_in[6];
    const float* wv    = (const float*)d_in[7];
    const float* bv    = (const float*)d_in[8];
    const float* wo    = (const float*)d_in[9];
    const float* bo    = (const float*)d_in[10];
    float* out = (float*)d_out;

    cudaFuncSetAttribute(gemm_mma, cudaFuncAttributeMaxDynamicSharedMemorySize,
                         SMEM_GEMM);

    __nv_bfloat16 *hT_hi, *hT_lo, *w_hi, *w_lo, *qT_hi, *qT_lo, *kT_hi, *kT_lo;
    __nv_bfloat16 *v_hi, *v_lo, *attn_hi, *attn_lo, *oT_hi, *oT_lo;
    float* S;
    cudaGetSymbolAddress((void**)&hT_hi, g_hT_hi);
    cudaGetSymbolAddress((void**)&hT_lo, g_hT_lo);
    cudaGetSymbolAddress((void**)&w_hi, g_w_hi);
    cudaGetSymbolAddress((void**)&w_lo, g_w_lo);
    cudaGetSymbolAddress((void**)&qT_hi, g_qT_hi);
    cudaGetSymbolAddress((void**)&qT_lo, g_qT_lo);
    cudaGetSymbolAddress((void**)&kT_hi, g_kT_hi);
    cudaGetSymbolAddress((void**)&kT_lo, g_kT_lo);
    cudaGetSymbolAddress((void**)&v_hi, g_v_hi);
    cudaGetSymbolAddress((void**)&v_lo, g_v_lo);
    cudaGetSymbolAddress((void**)&S, g_S);
    cudaGetSymbolAddress((void**)&attn_hi, g_attn_hi);
    cudaGetSymbolAddress((void**)&attn_lo, g_attn_lo);
    cudaGetSymbolAddress((void**)&oT_hi, g_oT_hi);
    cudaGetSymbolAddress((void**)&oT_lo, g_oT_lo);

    const float scale = 0.044194173824159216f;   // 512^-0.5
    const int WN = NCH * NCH;                    // 262144

    // 1) GroupNorm stats + normalize/transpose/split
    gn_stats_kernel<<<NB * NGROUPS, 256>>>(x);
    gn_tr_split_kernel<<<dim3(NSP / 32, NCH / 32, NB), dim3(32, 8)>>>(x, gamma, beta);

    // 2) weight splits
    split_kernel<<<WN / 256, 256>>>(wq, w_hi + 0 * WN, w_lo + 0 * WN, WN);
    split_kernel<<<WN / 256, 256>>>(wk, w_hi + 1 * WN, w_lo + 1 * WN, WN);
    split_kernel<<<WN / 256, 256>>>(wv, w_hi + 2 * WN, w_lo + 2 * WN, WN);
    split_kernel<<<WN / 256, 256>>>(wo, w_hi + 3 * WN, w_lo + 3 * WN, WN);

    // 3) qT[n,co] = hT[n,ci] . wq[co,ci]^T + bq   (M=4096, N=512, K=512)
    gemm_mma<<<dim3(NCH / 128, NSP / 128, NB), 256, SMEM_GEMM>>>(
        hT_hi, hT_lo, (long long)BCH_N, NCH,
        w_hi + 0 * WN, w_lo + 0 * WN, 0, NCH,
        nullptr, qT_hi, qT_lo, (long long)BCH_N, NCH,
        bq, 2, nullptr, 1.f, NCH);
    gemm_mma<<<dim3(NCH / 128, NSP / 128, NB), 256, SMEM_GEMM>>>(
        hT_hi, hT_lo, (long long)BCH_N, NCH,
        w_hi + 1 * WN, w_lo + 1 * WN, 0, NCH,
        nullptr, kT_hi, kT_lo, (long long)BCH_N, NCH,
        bk, 2, nullptr, 1.f, NCH);
    // v[c,n] = wv[c,ci] . hT[n,ci]^T + bv        (M=512, N=4096, K=512)
    gemm_mma<<<dim3(NSP / 128, NCH / 128, NB), 256, SMEM_GEMM>>>(
        w_hi + 2 * WN, w_lo + 2 * WN, 0, NCH,
        hT_hi, hT_lo, (long long)BCH_N, NCH,
        nullptr, v_hi, v_lo, (long long)BCH_N, NSP,
        bv, 1, nullptr, 1.f, NCH);

    // 4) S[i,j] = scale * qT[i,c] . kT[j,c]^T    (M=4096, N=4096, K=512)
    gemm_mma<<<dim3(NSP / 128, NSP / 128, NB), 256, SMEM_GEMM>>>(
        qT_hi, qT_lo, (long long)BCH_N, NCH,
        kT_hi, kT_lo, (long long)BCH_N, NCH,
        S, nullptr, nullptr, (long long)ATT_N, NSP,
        nullptr, 0, nullptr, scale, NCH);

    // 5) softmax rows -> attn hi/lo
    softmax_split_kernel<<<NB * NSP, 256>>>(S);

    // 6) oT[i,c] = attn[i,j] . v[c,j]^T          (M=4096, N=512, K=4096)
    gemm_mma<<<dim3(NCH / 128, NSP / 128, NB), 256, SMEM_GEMM>>>(
        attn_hi, attn_lo, (long long)ATT_N, NSP,
        v_hi, v_lo, (long long)BCH_N, NSP,
        nullptr, oT_hi, oT_lo, (long long)BCH_N, NCH,
        nullptr, 0, nullptr, 1.f, NSP);

    // 7) out[c,n] = wo[c,ci] . oT[n,ci]^T + bo + x  (M=512, N=4096, K=512)
    gemm_mma<<<dim3(NSP / 128, NCH / 128, NB), 256, SMEM_GEMM>>>(
        w_hi + 3 * WN, w_lo + 3 * WN, 0, NCH,
        oT_hi, oT_lo, (long long)BCH_N, NCH,
        out, nullptr, nullptr, (long long)BCH_N, NSP,
        bo, 1, x, 1.f, NCH);
}

// round 6
// speedup vs baseline: 4.4375x; 1.8549x over previous
#include <cuda_runtime.h>
#include <cuda_fp16.h>
#include <math.h>
#include <stdint.h>

#define NB 2
#define NCH 512
#define NSP 4096
#define NGROUPS 32
#define GELEMS 65536                       // 16 * 4096 per (b,g)
#define BCH_N ((size_t)NCH * NSP)          // 2097152
#define ATT_N ((size_t)NSP * NSP)          // 16777216

// ---------------- scratch (static device globals; no allocations) ------------
__device__ __half g_hT[NB * NSP * NCH];        // [b][n][c]
__device__ __half g_w[4][NCH * NCH];           // wq, wk, wv, wo
__device__ __half g_qT[NB * NSP * NCH];        // [b][n][c]
__device__ __half g_kT[NB * NSP * NCH];
__device__ __half g_v[NB * NCH * NSP];         // [b][c][n]
__device__ float  g_S[(size_t)NB * NSP * NSP];        // 134 MB
__device__ __half g_attn[(size_t)NB * NSP * NSP];     // [b][i][j]
__device__ __half g_oT[NB * NSP * NCH];        // [b][i][c]
__device__ float  g_stats[NB * NGROUPS * 2];

// ---------------- PTX helpers ------------------------------------------------
__device__ __forceinline__ uint32_t smem_u32(const void* p) {
    uint32_t a;
    asm("{ .reg .u64 t; cvta.to.shared.u64 t, %1; cvt.u32.u64 %0, t; }" : "=r"(a) : "l"(p));
    return a;
}
__device__ __forceinline__ void cpa16(uint32_t dst, const void* src) {
    asm volatile("cp.async.cg.shared.global [%0], [%1], 16;" :: "r"(dst), "l"(src));
}
#define CP_COMMIT() asm volatile("cp.async.commit_group;")
#define CP_WAIT(n)  asm volatile("cp.async.wait_group %0;" :: "n"(n) : "memory")

#define LDSM4(r, a) \
    asm volatile("ldmatrix.sync.aligned.m8n8.x4.shared.b16 {%0,%1,%2,%3}, [%4];" \
        : "=r"((r)[0]), "=r"((r)[1]), "=r"((r)[2]), "=r"((r)[3]) : "r"(a))
#define LDSM2(r, a) \
    asm volatile("ldmatrix.sync.aligned.m8n8.x2.shared.b16 {%0,%1}, [%2];" \
        : "=r"((r)[0]), "=r"((r)[1]) : "r"(a))
#define MMA_F16(d, a, b) \
    asm volatile("mma.sync.aligned.m16n8k16.row.col.f32.f16.f16.f32 " \
        "{%0,%1,%2,%3}, {%4,%5,%6,%7}, {%8,%9}, {%0,%1,%2,%3};" \
        : "+f"((d)[0]), "+f"((d)[1]), "+f"((d)[2]), "+f"((d)[3]) \
        : "r"((a)[0]), "r"((a)[1]), "r"((a)[2]), "r"((a)[3]), \
          "r"((b)[0]), "r"((b)[1]))

// ---------------- GroupNorm stats --------------------------------------------
__global__ void gn_stats_kernel(const float* __restrict__ x) {
    __shared__ float sh_s[256], sh_ss[256];
    const int bg = blockIdx.x;
    const float* p = x + (size_t)bg * GELEMS;
    float s = 0.f, ss = 0.f;
    for (int i = threadIdx.x * 4; i < GELEMS; i += 256 * 4) {
        float4 v = *(const float4*)&p[i];
        s  += v.x + v.y + v.z + v.w;
        ss += v.x * v.x + v.y * v.y + v.z * v.z + v.w * v.w;
    }
    sh_s[threadIdx.x] = s; sh_ss[threadIdx.x] = ss;
    __syncthreads();
    for (int st = 128; st > 0; st >>= 1) {
        if (threadIdx.x < st) {
            sh_s[threadIdx.x]  += sh_s[threadIdx.x + st];
            sh_ss[threadIdx.x] += sh_ss[threadIdx.x + st];
        }
        __syncthreads();
    }
    if (threadIdx.x == 0) {
        float mean = sh_s[0] * (1.f / GELEMS);
        float var  = sh_ss[0] * (1.f / GELEMS) - mean * mean;
        g_stats[bg * 2 + 0] = mean;
        g_stats[bg * 2 + 1] = rsqrtf(var + 1e-6f);
    }
}

// ------------- GroupNorm + transpose + fp16 convert --------------------------
// x [b][c][n] fp32  ->  hT [b][n][c] fp16
__global__ void gn_tr_kernel(const float* __restrict__ x,
                             const float* __restrict__ gamma,
                             const float* __restrict__ beta) {
    __shared__ float t[32][33];
    const int b  = blockIdx.z;
    const int c0 = blockIdx.y * 32;
    const int n0 = blockIdx.x * 32;
    const float* xb = x + (size_t)b * BCH_N;
    const int tx = threadIdx.x, ty = threadIdx.y;
#pragma unroll
    for (int r = 0; r < 4; r++) {
        int c = c0 + ty + r * 8;
        int bg = b * NGROUPS + (c >> 4);
        float mean = g_stats[bg * 2 + 0], rstd = g_stats[bg * 2 + 1];
        float ga = gamma[c] * rstd;
        float be = beta[c] - mean * ga;
        t[ty + r * 8][tx] = xb[(size_t)c * NSP + n0 + tx] * ga + be;
    }
    __syncthreads();
#pragma unroll
    for (int r = 0; r < 4; r++) {
        int n = n0 + ty + r * 8;
        int c = c0 + tx;
        g_hT[((size_t)b * NSP + n) * NCH + c] = __float2half(t[tx][ty + r * 8]);
    }
}

// ---------------- fp32 -> fp16 convert (weights) -----------------------------
__global__ void cvt_kernel(const float* __restrict__ src,
                           __half* __restrict__ dst, int n) {
    int i = blockIdx.x * blockDim.x + threadIdx.x;
    if (i < n) dst[i] = __float2half(src[i]);
}

// ---------------- softmax row -> fp16 ----------------------------------------
__global__ void softmax_kernel(const float* __restrict__ S) {
    __shared__ float row[NSP];
    __shared__ float red[256];
    const size_t r = blockIdx.x;
    const float* p = S + r * NSP;
    const int tid = threadIdx.x;

    float m = -1e30f;
    for (int i = tid; i < NSP; i += 256) {
        float v = p[i];
        row[i] = v;
        m = fmaxf(m, v);
    }
    red[tid] = m; __syncthreads();
    for (int st = 128; st > 0; st >>= 1) {
        if (tid < st) red[tid] = fmaxf(red[tid], red[tid + st]);
        __syncthreads();
    }
    m = red[0]; __syncthreads();

    float s = 0.f;
    for (int i = tid; i < NSP; i += 256) {
        float e = __expf(row[i] - m);
        row[i] = e;
        s += e;
    }
    red[tid] = s; __syncthreads();
    for (int st = 128; st > 0; st >>= 1) {
        if (tid < st) red[tid] += red[tid + st];
        __syncthreads();
    }
    float inv = 1.f / red[0];
    size_t base = r * NSP;
    for (int i = tid; i < NSP; i += 256)
        g_attn[base + i] = __float2half(row[i] * inv);
}

// ---------------- fp16 GEMM via mma.sync (HMMA) ------------------------------
// C[M,N] = alpha * A[M,K] . B[N,K]^T  (+ bias) (+ resid)
// CTA tile 128x128x32, 8 warps (2x4), warp tile 64x32, cp.async double buffer.
// SMEM rows padded to 80B (64B data + 16B) -> conflict-free ldmatrix.
#define ROWB 80
#define T_A 0
#define T_B 10240
#define STAGE  20480
#define SMEM_GEMM (2 * STAGE)     // 40960

__global__ void __launch_bounds__(256, 1)
gemm_f16(const __half* __restrict__ A, long long sA, int lda,
         const __half* __restrict__ B, long long sB, int ldb,
         float* __restrict__ Cf, __half* __restrict__ Ch,
         long long sC, int ldc,
         const float* __restrict__ bias, int bias_mode,
         const float* __restrict__ resid, float alpha, int K) {
    extern __shared__ char smem[];
    const uint32_t sb = smem_u32(smem);
    const int tid = threadIdx.x;
    const int wid = tid >> 5, lane = tid & 31;
    const int wm = wid >> 2, wn = wid & 3;        // 2 x 4 warp grid
    const int bz = blockIdx.z;
    A += (size_t)bz * sA;
    B += (size_t)bz * sB;
    const size_t cOff = (size_t)bz * sC;
    const int m0 = blockIdx.y * 128;
    const int n0 = blockIdx.x * 128;

    float acc[4][4][4];
#pragma unroll
    for (int i = 0; i < 4; i++)
#pragma unroll
        for (int j = 0; j < 4; j++)
#pragma unroll
            for (int r = 0; r < 4; r++) acc[i][j][r] = 0.f;

    const int nch = K / 32;

    const int lrow = tid >> 2;            // 0..63
    const int lu   = tid & 3;             // 16B chunk within 64B row
    {
        const uint32_t stg = sb;
#pragma unroll
        for (int i = 0; i < 2; i++) {
            int row = lrow + i * 64;
            uint32_t so = row * ROWB + lu * 16;
            cpa16(stg + T_A + so, A + (size_t)(m0 + row) * lda + lu * 8);
            cpa16(stg + T_B + so, B + (size_t)(n0 + row) * ldb + lu * 8);
        }
        CP_COMMIT();
    }

    for (int c = 0; c < nch; c++) {
        if (c + 1 < nch) {
            const uint32_t stg = sb + ((c + 1) & 1) * STAGE;
            const int k0 = (c + 1) * 32;
#pragma unroll
            for (int i = 0; i < 2; i++) {
                int row = lrow + i * 64;
                uint32_t so = row * ROWB + lu * 16;
                cpa16(stg + T_A + so, A + (size_t)(m0 + row) * lda + k0 + lu * 8);
                cpa16(stg + T_B + so, B + (size_t)(n0 + row) * ldb + k0 + lu * 8);
            }
            CP_COMMIT();
            CP_WAIT(1);
        } else {
            CP_WAIT(0);
        }
        __syncthreads();

        const uint32_t stg = sb + (c & 1) * STAGE;
        const int lr = lane & 15, lc = lane >> 4;
        const int br = lane & 7, bh2 = (lane & 15) >> 3;
#pragma unroll
        for (int kk = 0; kk < 2; kk++) {
            uint32_t af[4][4], bf[4][2];
#pragma unroll
            for (int mi = 0; mi < 4; mi++) {
                uint32_t a = stg + T_A + (uint32_t)(wm * 64 + mi * 16 + lr) * ROWB
                           + lc * 16 + kk * 32;
                LDSM4(af[mi], a);
            }
#pragma unroll
            for (int ni = 0; ni < 4; ni++) {
                uint32_t b = stg + T_B + (uint32_t)(wn * 32 + ni * 8 + br) * ROWB
                           + bh2 * 16 + kk * 32;
                LDSM2(bf[ni], b);
            }
#pragma unroll
            for (int mi = 0; mi < 4; mi++)
#pragma unroll
                for (int ni = 0; ni < 4; ni++)
                    MMA_F16(acc[mi][ni], af[mi], bf[ni]);
        }
        __syncthreads();
    }

    // ---- epilogue ----
    const int r = lane >> 2;
    const int cb = 2 * (lane & 3);
#pragma unroll
    for (int mi = 0; mi < 4; mi++) {
#pragma unroll
        for (int h = 0; h < 2; h++) {
            const int m = m0 + wm * 64 + mi * 16 + h * 8 + r;
            const float bm = (bias_mode == 1) ? bias[m] : 0.f;
#pragma unroll
            for (int ni = 0; ni < 4; ni++) {
                const int n = n0 + wn * 32 + ni * 8 + cb;
                float v0 = acc[mi][ni][h * 2 + 0] * alpha + bm;
                float v1 = acc[mi][ni][h * 2 + 1] * alpha + bm;
                if (bias_mode == 2) { v0 += bias[n]; v1 += bias[n + 1]; }
                const size_t off = cOff + (size_t)m * ldc + n;
                if (Cf) {
                    if (resid) { v0 += resid[off]; v1 += resid[off + 1]; }
                    float2 o; o.x = v0; o.y = v1;
                    *(float2*)(Cf + off) = o;
                } else {
                    __half2 p;
                    p.x = __float2half(v0);
                    p.y = __float2half(v1);
                    *(__half2*)(Ch + off) = p;
                }
            }
        }
    }
}

// ---------------- launch -----------------------------------------------------
extern "C" void kernel_launch(void* const* d_in, const int* in_sizes, int n_in,
                              void* d_out, int out_size) {
    const float* x     = (const float*)d_in[0];
    const float* gamma = (const float*)d_in[1];
    const float* beta  = (const float*)d_in[2];
    const float* wq    = (const float*)d_in[3];
    const float* bq    = (const float*)d_in[4];
    const float* wk    = (const float*)d_in[5];
    const float* bk    = (const float*)d_in[6];
    const float* wv    = (const float*)d_in[7];
    const float* bv    = (const float*)d_in[8];
    const float* wo    = (const float*)d_in[9];
    const float* bo    = (const float*)d_in[10];
    float* out = (float*)d_out;

    cudaFuncSetAttribute(gemm_f16, cudaFuncAttributeMaxDynamicSharedMemorySize,
                         SMEM_GEMM);

    __half *hT, *w, *qT, *kT, *v, *attn, *oT;
    float* S;
    cudaGetSymbolAddress((void**)&hT, g_hT);
    cudaGetSymbolAddress((void**)&w, g_w);
    cudaGetSymbolAddress((void**)&qT, g_qT);
    cudaGetSymbolAddress((void**)&kT, g_kT);
    cudaGetSymbolAddress((void**)&v, g_v);
    cudaGetSymbolAddress((void**)&S, g_S);
    cudaGetSymbolAddress((void**)&attn, g_attn);
    cudaGetSymbolAddress((void**)&oT, g_oT);

    const float scale = 0.044194173824159216f;   // 512^-0.5
    const int WN = NCH * NCH;                    // 262144

    // 1) GroupNorm stats + normalize/transpose/convert
    gn_stats_kernel<<<NB * NGROUPS, 256>>>(x);
    gn_tr_kernel<<<dim3(NSP / 32, NCH / 32, NB), dim3(32, 8)>>>(x, gamma, beta);

    // 2) weight converts
    cvt_kernel<<<WN / 256, 256>>>(wq, w + 0 * WN, WN);
    cvt_kernel<<<WN / 256, 256>>>(wk, w + 1 * WN, WN);
    cvt_kernel<<<WN / 256, 256>>>(wv, w + 2 * WN, WN);
    cvt_kernel<<<WN / 256, 256>>>(wo, w + 3 * WN, WN);

    // 3) qT[n,co] = hT[n,ci] . wq[co,ci]^T + bq   (M=4096, N=512, K=512)
    gemm_f16<<<dim3(NCH / 128, NSP / 128, NB), 256, SMEM_GEMM>>>(
        hT, (long long)BCH_N, NCH, w + 0 * WN, 0, NCH,
        nullptr, qT, (long long)BCH_N, NCH, bq, 2, nullptr, 1.f, NCH);
    gemm_f16<<<dim3(NCH / 128, NSP / 128, NB), 256, SMEM_GEMM>>>(
        hT, (long long)BCH_N, NCH, w + 1 * WN, 0, NCH,
        nullptr, kT, (long long)BCH_N, NCH, bk, 2, nullptr, 1.f, NCH);
    // v[c,n] = wv[c,ci] . hT[n,ci]^T + bv        (M=512, N=4096, K=512)
    gemm_f16<<<dim3(NSP / 128, NCH / 128, NB), 256, SMEM_GEMM>>>(
        w + 2 * WN, 0, NCH, hT, (long long)BCH_N, NCH,
        nullptr, v, (long long)BCH_N, NSP, bv, 1, nullptr, 1.f, NCH);

    // 4) S[i,j] = scale * qT[i,c] . kT[j,c]^T    (M=4096, N=4096, K=512)
    gemm_f16<<<dim3(NSP / 128, NSP / 128, NB), 256, SMEM_GEMM>>>(
        qT, (long long)BCH_N, NCH, kT, (long long)BCH_N, NCH,
        S, nullptr, (long long)ATT_N, NSP, nullptr, 0, nullptr, scale, NCH);

    // 5) softmax rows -> attn fp16
    softmax_kernel<<<NB * NSP, 256>>>(S);

    // 6) oT[i,c] = attn[i,j] . v[c,j]^T          (M=4096, N=512, K=4096)
    gemm_f16<<<dim3(NCH / 128, NSP / 128, NB), 256, SMEM_GEMM>>>(
        attn, (long long)ATT_N, NSP, v, (long long)BCH_N, NSP,
        nullptr, oT, (long long)BCH_N, NCH, nullptr, 0, nullptr, 1.f, NSP);

    // 7) out[c,n] = wo[c,ci] . oT[n,ci]^T + bo + x  (M=512, N=4096, K=512)
    gemm_f16<<<dim3(NSP / 128, NCH / 128, NB), 256, SMEM_GEMM>>>(
        w + 3 * WN, 0, NCH, oT, (long long)BCH_N, NCH,
        out, nullptr, (long long)BCH_N, NSP, bo, 1, x, 1.f, NCH);
}

// round 7
// speedup vs baseline: 5.4868x; 1.2365x over previous
#include <cuda_runtime.h>
#include <cuda_fp16.h>
#include <math.h>
#include <stdint.h>

#define NB 2
#define NCH 512
#define NSP 4096
#define NGROUPS 32
#define GELEMS 65536                       // 16 * 4096 per (b,g)
#define BCH_N ((size_t)NCH * NSP)          // 2097152
#define ATT_N ((size_t)NSP * NSP)          // 16777216

// ---------------- scratch (static device globals; no allocations) ------------
__device__ __half g_hT[NB * NSP * NCH];        // [b][n][c]
__device__ __half g_w[4][NCH * NCH];           // wq, wk, wv, wo
__device__ __half g_qT[NB * NSP * NCH];        // [b][n][c]
__device__ __half g_kT[NB * NSP * NCH];
__device__ __half g_v[NB * NCH * NSP];         // [b][c][n]
__device__ float  g_S[(size_t)NB * NSP * NSP];        // 134 MB
__device__ __half g_attn[(size_t)NB * NSP * NSP];     // [b][i][j]
__device__ __half g_oT[NB * NSP * NCH];        // [b][i][c]
__device__ float  g_stats[NB * NGROUPS * 2];

// ---------------- PTX helpers ------------------------------------------------
__device__ __forceinline__ uint32_t smem_u32(const void* p) {
    uint32_t a;
    asm("{ .reg .u64 t; cvta.to.shared.u64 t, %1; cvt.u32.u64 %0, t; }" : "=r"(a) : "l"(p));
    return a;
}
__device__ __forceinline__ void cpa16(uint32_t dst, const void* src) {
    asm volatile("cp.async.cg.shared.global [%0], [%1], 16;" :: "r"(dst), "l"(src));
}
#define CP_COMMIT() asm volatile("cp.async.commit_group;")
#define CP_WAIT(n)  asm volatile("cp.async.wait_group %0;" :: "n"(n) : "memory")

#define LDSM4(r, a) \
    asm volatile("ldmatrix.sync.aligned.m8n8.x4.shared.b16 {%0,%1,%2,%3}, [%4];" \
        : "=r"((r)[0]), "=r"((r)[1]), "=r"((r)[2]), "=r"((r)[3]) : "r"(a))
#define MMA_F16(d, a, b) \
    asm volatile("mma.sync.aligned.m16n8k16.row.col.f32.f16.f16.f32 " \
        "{%0,%1,%2,%3}, {%4,%5,%6,%7}, {%8,%9}, {%0,%1,%2,%3};" \
        : "+f"((d)[0]), "+f"((d)[1]), "+f"((d)[2]), "+f"((d)[3]) \
        : "r"((a)[0]), "r"((a)[1]), "r"((a)[2]), "r"((a)[3]), \
          "r"((b)[0]), "r"((b)[1]))

// ---------------- GroupNorm stats --------------------------------------------
__global__ void gn_stats_kernel(const float* __restrict__ x) {
    __shared__ float sh_s[256], sh_ss[256];
    const int bg = blockIdx.x;
    const float* p = x + (size_t)bg * GELEMS;
    float s = 0.f, ss = 0.f;
    for (int i = threadIdx.x * 4; i < GELEMS; i += 256 * 4) {
        float4 v = *(const float4*)&p[i];
        s  += v.x + v.y + v.z + v.w;
        ss += v.x * v.x + v.y * v.y + v.z * v.z + v.w * v.w;
    }
    sh_s[threadIdx.x] = s; sh_ss[threadIdx.x] = ss;
    __syncthreads();
    for (int st = 128; st > 0; st >>= 1) {
        if (threadIdx.x < st) {
            sh_s[threadIdx.x]  += sh_s[threadIdx.x + st];
            sh_ss[threadIdx.x] += sh_ss[threadIdx.x + st];
        }
        __syncthreads();
    }
    if (threadIdx.x == 0) {
        float mean = sh_s[0] * (1.f / GELEMS);
        float var  = sh_ss[0] * (1.f / GELEMS) - mean * mean;
        g_stats[bg * 2 + 0] = mean;
        g_stats[bg * 2 + 1] = rsqrtf(var + 1e-6f);
    }
}

// ------------- GroupNorm + transpose + fp16 convert --------------------------
__global__ void gn_tr_kernel(const float* __restrict__ x,
                             const float* __restrict__ gamma,
                             const float* __restrict__ beta) {
    __shared__ float t[32][33];
    const int b  = blockIdx.z;
    const int c0 = blockIdx.y * 32;
    const int n0 = blockIdx.x * 32;
    const float* xb = x + (size_t)b * BCH_N;
    const int tx = threadIdx.x, ty = threadIdx.y;
#pragma unroll
    for (int r = 0; r < 4; r++) {
        int c = c0 + ty + r * 8;
        int bg = b * NGROUPS + (c >> 4);
        float mean = g_stats[bg * 2 + 0], rstd = g_stats[bg * 2 + 1];
        float ga = gamma[c] * rstd;
        float be = beta[c] - mean * ga;
        t[ty + r * 8][tx] = xb[(size_t)c * NSP + n0 + tx] * ga + be;
    }
    __syncthreads();
#pragma unroll
    for (int r = 0; r < 4; r++) {
        int n = n0 + ty + r * 8;
        int c = c0 + tx;
        g_hT[((size_t)b * NSP + n) * NCH + c] = __float2half(t[tx][ty + r * 8]);
    }
}

// ---------------- fp32 -> fp16 convert, all 4 weights in one launch ----------
__global__ void cvt4_kernel(const float* __restrict__ a, const float* __restrict__ b,
                            const float* __restrict__ c, const float* __restrict__ d,
                            __half* __restrict__ dst) {
    const int WN = NCH * NCH;
    int i = blockIdx.x * blockDim.x + threadIdx.x;
    dst[0 * WN + i] = __float2half(a[i]);
    dst[1 * WN + i] = __float2half(b[i]);
    dst[2 * WN + i] = __float2half(c[i]);
    dst[3 * WN + i] = __float2half(d[i]);
}

// ---------------- softmax row -> fp16 ----------------------------------------
__global__ void softmax_kernel(const float* __restrict__ S) {
    __shared__ float row[NSP];
    __shared__ float red[256];
    const size_t r = blockIdx.x;
    const float* p = S + r * NSP;
    const int tid = threadIdx.x;

    float m = -1e30f;
    for (int i = tid; i < NSP; i += 256) {
        float v = p[i];
        row[i] = v;
        m = fmaxf(m, v);
    }
    red[tid] = m; __syncthreads();
    for (int st = 128; st > 0; st >>= 1) {
        if (tid < st) red[tid] = fmaxf(red[tid], red[tid + st]);
        __syncthreads();
    }
    m = red[0]; __syncthreads();

    float s = 0.f;
    for (int i = tid; i < NSP; i += 256) {
        float e = __expf(row[i] - m);
        row[i] = e;
        s += e;
    }
    red[tid] = s; __syncthreads();
    for (int st = 128; st > 0; st >>= 1) {
        if (tid < st) red[tid] += red[tid + st];
        __syncthreads();
    }
    float inv = 1.f / red[0];
    size_t base = r * NSP;
    for (int i = tid; i < NSP; i += 256)
        g_attn[base + i] = __float2half(row[i] * inv);
}

// ---------------- fp16 GEMM via mma.sync (HMMA) ------------------------------
// C[M,N] = alpha * A[M,K] . B[N,K]^T  (+ bias) (+ resid)
// CTA tile 128x256x32, 8 warps (2x4), warp tile 64x64, 3-stage cp.async.
// SMEM rows padded to 80B (64B data + 16B) -> conflict-free ldmatrix.
#define ROWB 80
#define T_A 0
#define T_B 10240
#define STAGE 30720
#define NST 3
#define SMEM_GEMM (NST * STAGE)     // 92160

__global__ void __launch_bounds__(256, 1)
gemm_f16(const __half* __restrict__ A, long long sA, int lda,
         const __half* __restrict__ B, long long sB, int ldb,
         float* __restrict__ Cf, __half* __restrict__ Ch,
         long long sC, int ldc,
         const float* __restrict__ bias, int bias_mode,
         const float* __restrict__ resid, float alpha, int K) {
    extern __shared__ char smem[];
    const uint32_t sb = smem_u32(smem);
    const int tid = threadIdx.x;
    const int wid = tid >> 5, lane = tid & 31;
    const int wm = wid >> 2, wn = wid & 3;        // 2 x 4 warp grid
    const int bz = blockIdx.z;
    A += (size_t)bz * sA;
    B += (size_t)bz * sB;
    const size_t cOff = (size_t)bz * sC;
    const int m0 = blockIdx.y * 128;
    const int n0 = blockIdx.x * 256;

    float acc[4][8][4];
#pragma unroll
    for (int i = 0; i < 4; i++)
#pragma unroll
        for (int j = 0; j < 8; j++)
#pragma unroll
            for (int r = 0; r < 4; r++) acc[i][j][r] = 0.f;

    const int nch = K / 32;
    const int arow = tid >> 2, au = tid & 3;        // A: 2 iters of 128 rows? no:
    // A loads: 512 = 128 rows * 4 chunks -> idx = tid + i*256, i<2
    // B loads: 1024 = 256 rows * 4 chunks -> idx = tid + i*256, i<4

    // ---- prologue: stages 0,1 ----
#pragma unroll
    for (int s = 0; s < NST - 1; s++) {
        const uint32_t stg = sb + s * STAGE;
        const int k0 = s * 32;
#pragma unroll
        for (int i = 0; i < 2; i++) {
            int idx = tid + i * 256;
            int row = idx >> 2, u = idx & 3;
            cpa16(stg + T_A + row * ROWB + u * 16,
                  A + (size_t)(m0 + row) * lda + k0 + u * 8);
        }
#pragma unroll
        for (int i = 0; i < 4; i++) {
            int idx = tid + i * 256;
            int row = idx >> 2, u = idx & 3;
            cpa16(stg + T_B + row * ROWB + u * 16,
                  B + (size_t)(n0 + row) * ldb + k0 + u * 8);
        }
        CP_COMMIT();
    }

    const int lr = lane & 15, lc = lane >> 4;                 // A frag addr
    const int nr = ((lane >> 4) << 3) | (lane & 7);           // B frag addr
    const int kc = (lane >> 3) & 1;

    for (int c = 0; c < nch; c++) {
        CP_WAIT(NST - 2);
        __syncthreads();
        // issue loads for stage c + NST - 1
        if (c + NST - 1 < nch) {
            const uint32_t stg = sb + ((c + NST - 1) % NST) * STAGE;
            const int k0 = (c + NST - 1) * 32;
#pragma unroll
            for (int i = 0; i < 2; i++) {
                int idx = tid + i * 256;
                int row = idx >> 2, u = idx & 3;
                cpa16(stg + T_A + row * ROWB + u * 16,
                      A + (size_t)(m0 + row) * lda + k0 + u * 8);
            }
#pragma unroll
            for (int i = 0; i < 4; i++) {
                int idx = tid + i * 256;
                int row = idx >> 2, u = idx & 3;
                cpa16(stg + T_B + row * ROWB + u * 16,
                      B + (size_t)(n0 + row) * ldb + k0 + u * 8);
            }
        }
        CP_COMMIT();

        const uint32_t stg = sb + (c % NST) * STAGE;
#pragma unroll
        for (int kk = 0; kk < 2; kk++) {
            uint32_t af[4][4], bf[4][4];
#pragma unroll
            for (int mi = 0; mi < 4; mi++) {
                uint32_t a = stg + T_A + (uint32_t)(wm * 64 + mi * 16 + lr) * ROWB
                           + lc * 16 + kk * 32;
                LDSM4(af[mi], a);
            }
#pragma unroll
            for (int nt = 0; nt < 4; nt++) {
                uint32_t b = stg + T_B + (uint32_t)(wn * 64 + nt * 16 + nr) * ROWB
                           + kc * 16 + kk * 32;
                LDSM4(bf[nt], b);
            }
#pragma unroll
            for (int mi = 0; mi < 4; mi++)
#pragma unroll
                for (int nt = 0; nt < 4; nt++) {
                    MMA_F16(acc[mi][2 * nt + 0], af[mi], bf[nt]);
                    MMA_F16(acc[mi][2 * nt + 1], af[mi], (bf[nt] + 2));
                }
        }
    }

    // ---- epilogue ----
    const int r = lane >> 2;
    const int cb = 2 * (lane & 3);
#pragma unroll
    for (int mi = 0; mi < 4; mi++) {
#pragma unroll
        for (int h = 0; h < 2; h++) {
            const int m = m0 + wm * 64 + mi * 16 + h * 8 + r;
            const float bm = (bias_mode == 1) ? bias[m] : 0.f;
#pragma unroll
            for (int ni = 0; ni < 8; ni++) {
                const int n = n0 + wn * 64 + ni * 8 + cb;
                float v0 = acc[mi][ni][h * 2 + 0] * alpha + bm;
                float v1 = acc[mi][ni][h * 2 + 1] * alpha + bm;
                if (bias_mode == 2) { v0 += bias[n]; v1 += bias[n + 1]; }
                const size_t off = cOff + (size_t)m * ldc + n;
                if (Cf) {
                    if (resid) { v0 += resid[off]; v1 += resid[off + 1]; }
                    float2 o; o.x = v0; o.y = v1;
                    *(float2*)(Cf + off) = o;
                } else {
                    __half2 p;
                    p.x = __float2half(v0);
                    p.y = __float2half(v1);
                    *(__half2*)(Ch + off) = p;
                }
            }
        }
    }
}

// ---------------- launch -----------------------------------------------------
extern "C" void kernel_launch(void* const* d_in, const int* in_sizes, int n_in,
                              void* d_out, int out_size) {
    const float* x     = (const float*)d_in[0];
    const float* gamma = (const float*)d_in[1];
    const float* beta  = (const float*)d_in[2];
    const float* wq    = (const float*)d_in[3];
    const float* bq    = (const float*)d_in[4];
    const float* wk    = (const float*)d_in[5];
    const float* bk    = (const float*)d_in[6];
    const float* wv    = (const float*)d_in[7];
    const float* bv    = (const float*)d_in[8];
    const float* wo    = (const float*)d_in[9];
    const float* bo    = (const float*)d_in[10];
    float* out = (float*)d_out;

    cudaFuncSetAttribute(gemm_f16, cudaFuncAttributeMaxDynamicSharedMemorySize,
                         SMEM_GEMM);

    __half *hT, *w, *qT, *kT, *v, *attn, *oT;
    float* S;
    cudaGetSymbolAddress((void**)&hT, g_hT);
    cudaGetSymbolAddress((void**)&w, g_w);
    cudaGetSymbolAddress((void**)&qT, g_qT);
    cudaGetSymbolAddress((void**)&kT, g_kT);
    cudaGetSymbolAddress((void**)&v, g_v);
    cudaGetSymbolAddress((void**)&S, g_S);
    cudaGetSymbolAddress((void**)&attn, g_attn);
    cudaGetSymbolAddress((void**)&oT, g_oT);

    const float scale = 0.044194173824159216f;   // 512^-0.5
    const int WN = NCH * NCH;                    // 262144

    // 1) GroupNorm stats + normalize/transpose/convert
    gn_stats_kernel<<<NB * NGROUPS, 256>>>(x);
    gn_tr_kernel<<<dim3(NSP / 32, NCH / 32, NB), dim3(32, 8)>>>(x, gamma, beta);

    // 2) weight converts (one launch)
    cvt4_kernel<<<WN / 256, 256>>>(wq, wk, wv, wo, w);

    // 3) qT[n,co] = hT[n,ci] . wq[co,ci]^T + bq   (M=4096, N=512, K=512)
    gemm_f16<<<dim3(NCH / 256, NSP / 128, NB), 256, SMEM_GEMM>>>(
        hT, (long long)BCH_N, NCH, w + 0 * WN, 0, NCH,
        nullptr, qT, (long long)BCH_N, NCH, bq, 2, nullptr, 1.f, NCH);
    gemm_f16<<<dim3(NCH / 256, NSP / 128, NB), 256, SMEM_GEMM>>>(
        hT, (long long)BCH_N, NCH, w + 1 * WN, 0, NCH,
        nullptr, kT, (long long)BCH_N, NCH, bk, 2, nullptr, 1.f, NCH);
    // v[c,n] = wv[c,ci] . hT[n,ci]^T + bv        (M=512, N=4096, K=512)
    gemm_f16<<<dim3(NSP / 256, NCH / 128, NB), 256, SMEM_GEMM>>>(
        w + 2 * WN, 0, NCH, hT, (long long)BCH_N, NCH,
        nullptr, v, (long long)BCH_N, NSP, bv, 1, nullptr, 1.f, NCH);

    // 4) S[i,j] = scale * qT[i,c] . kT[j,c]^T    (M=4096, N=4096, K=512)
    gemm_f16<<<dim3(NSP / 256, NSP / 128, NB), 256, SMEM_GEMM>>>(
        qT, (long long)BCH_N, NCH, kT, (long long)BCH_N, NCH,
        S, nullptr, (long long)ATT_N, NSP, nullptr, 0, nullptr, scale, NCH);

    // 5) softmax rows -> attn fp16
    softmax_kernel<<<NB * NSP, 256>>>(S);

    // 6) oT[i,c] = attn[i,j] . v[c,j]^T          (M=4096, N=512, K=4096)
    gemm_f16<<<dim3(NCH / 256, NSP / 128, NB), 256, SMEM_GEMM>>>(
        attn, (long long)ATT_N, NSP, v, (long long)BCH_N, NSP,
        nullptr, oT, (long long)BCH_N, NCH, nullptr, 0, nullptr, 1.f, NSP);

    // 7) out[c,n] = wo[c,ci] . oT[n,ci]^T + bo + x  (M=512, N=4096, K=512)
    gemm_f16<<<dim3(NSP / 256, NCH / 128, NB), 256, SMEM_GEMM>>>(
        w + 3 * WN, 0, NCH, oT, (long long)BCH_N, NCH,
        out, nullptr, (long long)BCH_N, NSP, bo, 1, x, 1.f, NCH);
}

// round 11
// speedup vs baseline: 5.5412x; 1.0099x over previous
#include <cuda_runtime.h>
#include <cuda_fp16.h>
#include <math.h>
#include <stdint.h>

#define NB 2
#define NCH 512
#define NSP 4096
#define NGROUPS 32
#define GELEMS 65536                       // 16 * 4096 per (b,g)
#define BCH_N ((size_t)NCH * NSP)          // 2097152
#define ATT_N ((size_t)NSP * NSP)          // 16777216

// ---------------- scratch (static device globals; no allocations) ------------
__device__ __half g_hT[NB * NSP * NCH];        // [b][n][c]
__device__ __half g_w[4][NCH * NCH];           // wq, wk, wv, wo
__device__ __half g_qT[NB * NSP * NCH];        // [b][n][c]
__device__ __half g_kT[NB * NSP * NCH];
__device__ __half g_v[NB * NCH * NSP];         // [b][c][n]
__device__ float  g_S[(size_t)NB * NSP * NSP];        // 134 MB
__device__ __half g_attn[(size_t)NB * NSP * NSP];     // [b][i][j]
__device__ __half g_oT[NB * NSP * NCH];        // [b][i][c]
__device__ float  g_stats[NB * NGROUPS * 2];

// ---------------- PTX helpers ------------------------------------------------
__device__ __forceinline__ uint32_t smem_u32(const void* p) {
    uint32_t a;
    asm("{ .reg .u64 t; cvta.to.shared.u64 t, %1; cvt.u32.u64 %0, t; }" : "=r"(a) : "l"(p));
    return a;
}
__device__ __forceinline__ void cpa16(uint32_t dst, const void* src) {
    asm volatile("cp.async.cg.shared.global [%0], [%1], 16;" :: "r"(dst), "l"(src));
}
#define CP_COMMIT() asm volatile("cp.async.commit_group;")
#define CP_WAIT(n)  asm volatile("cp.async.wait_group %0;" :: "n"(n) : "memory")

#define LDSM4(r, a) \
    asm volatile("ldmatrix.sync.aligned.m8n8.x4.shared.b16 {%0,%1,%2,%3}, [%4];" \
        : "=r"((r)[0]), "=r"((r)[1]), "=r"((r)[2]), "=r"((r)[3]) : "r"(a))
#define MMA_F16(d, a, b) \
    asm volatile("mma.sync.aligned.m16n8k16.row.col.f32.f16.f16.f32 " \
        "{%0,%1,%2,%3}, {%4,%5,%6,%7}, {%8,%9}, {%0,%1,%2,%3};" \
        : "+f"((d)[0]), "+f"((d)[1]), "+f"((d)[2]), "+f"((d)[3]) \
        : "r"((a)[0]), "r"((a)[1]), "r"((a)[2]), "r"((a)[3]), \
          "r"((b)[0]), "r"((b)[1]))

// ---------------- GroupNorm stats --------------------------------------------
__global__ void gn_stats_kernel(const float* __restrict__ x) {
    __shared__ float sh_s[256], sh_ss[256];
    const int bg = blockIdx.x;
    const float* p = x + (size_t)bg * GELEMS;
    float s = 0.f, ss = 0.f;
    for (int i = threadIdx.x * 4; i < GELEMS; i += 256 * 4) {
        float4 v = *(const float4*)&p[i];
        s  += v.x + v.y + v.z + v.w;
        ss += v.x * v.x + v.y * v.y + v.z * v.z + v.w * v.w;
    }
    sh_s[threadIdx.x] = s; sh_ss[threadIdx.x] = ss;
    __syncthreads();
    for (int st = 128; st > 0; st >>= 1) {
        if (threadIdx.x < st) {
            sh_s[threadIdx.x]  += sh_s[threadIdx.x + st];
            sh_ss[threadIdx.x] += sh_ss[threadIdx.x + st];
        }
        __syncthreads();
    }
    if (threadIdx.x == 0) {
        float mean = sh_s[0] * (1.f / GELEMS);
        float var  = sh_ss[0] * (1.f / GELEMS) - mean * mean;
        g_stats[bg * 2 + 0] = mean;
        g_stats[bg * 2 + 1] = rsqrtf(var + 1e-6f);
    }
}

// ------------- GroupNorm + transpose + fp16 convert --------------------------
__global__ void gn_tr_kernel(const float* __restrict__ x,
                             const float* __restrict__ gamma,
                             const float* __restrict__ beta) {
    __shared__ float t[32][33];
    const int b  = blockIdx.z;
    const int c0 = blockIdx.y * 32;
    const int n0 = blockIdx.x * 32;
    const float* xb = x + (size_t)b * BCH_N;
    const int tx = threadIdx.x, ty = threadIdx.y;
#pragma unroll
    for (int r = 0; r < 4; r++) {
        int c = c0 + ty + r * 8;
        int bg = b * NGROUPS + (c >> 4);
        float mean = g_stats[bg * 2 + 0], rstd = g_stats[bg * 2 + 1];
        float ga = gamma[c] * rstd;
        float be = beta[c] - mean * ga;
        t[ty + r * 8][tx] = xb[(size_t)c * NSP + n0 + tx] * ga + be;
    }
    __syncthreads();
#pragma unroll
    for (int r = 0; r < 4; r++) {
        int n = n0 + ty + r * 8;
        int c = c0 + tx;
        g_hT[((size_t)b * NSP + n) * NCH + c] = __float2half(t[tx][ty + r * 8]);
    }
}

// ---------------- fp32 -> fp16 convert, all 4 weights in one launch ----------
__global__ void cvt4_kernel(const float* __restrict__ a, const float* __restrict__ b,
                            const float* __restrict__ c, const float* __restrict__ d,
                            __half* __restrict__ dst) {
    const int WN = NCH * NCH;
    int i = blockIdx.x * blockDim.x + threadIdx.x;
    dst[0 * WN + i] = __float2half(a[i]);
    dst[1 * WN + i] = __float2half(b[i]);
    dst[2 * WN + i] = __float2half(c[i]);
    dst[3 * WN + i] = __float2half(d[i]);
}

// ---------------- softmax row -> fp16 ----------------------------------------
__global__ void softmax_kernel(const float* __restrict__ S) {
    __shared__ float row[NSP];
    __shared__ float red[256];
    const size_t r = blockIdx.x;
    const float* p = S + r * NSP;
    const int tid = threadIdx.x;

    float m = -1e30f;
    for (int i = tid; i < NSP; i += 256) {
        float v = p[i];
        row[i] = v;
        m = fmaxf(m, v);
    }
    red[tid] = m; __syncthreads();
    for (int st = 128; st > 0; st >>= 1) {
        if (tid < st) red[tid] = fmaxf(red[tid], red[tid + st]);
        __syncthreads();
    }
    m = red[0]; __syncthreads();

    float s = 0.f;
    for (int i = tid; i < NSP; i += 256) {
        float e = __expf(row[i] - m);
        row[i] = e;
        s += e;
    }
    red[tid] = s; __syncthreads();
    for (int st = 128; st > 0; st >>= 1) {
        if (tid < st) red[tid] += red[tid + st];
        __syncthreads();
    }
    float inv = 1.f / red[0];
    size_t base = r * NSP;
    for (int i = tid; i < NSP; i += 256)
        g_attn[base + i] = __float2half(row[i] * inv);
}

// ---------------- fp16 GEMM via mma.sync (HMMA) ------------------------------
// C[M,N] = alpha * A[M,K] . B[N,K]^T  (+ bias) (+ resid)
// CTA tile 128x256x32, 16 warps (2x8), warp tile 64x32, 3-stage cp.async.
// SMEM rows padded to 80B (64B data + 16B) -> conflict-free ldmatrix.
#define ROWB 80
#define T_A 0
#define T_B 10240
#define STAGE 30720
#define NST 3
#define SMEM_GEMM (NST * STAGE)     // 92160
#define NTHR 512

__global__ void __launch_bounds__(NTHR, 1)
gemm_f16(const __half* __restrict__ A, long long sA, int lda,
         const __half* __restrict__ B, long long sB, int ldb,
         float* __restrict__ Cf, __half* __restrict__ Ch,
         long long sC, int ldc,
         const float* __restrict__ bias, int bias_mode,
         const float* __restrict__ resid, float alpha, int K) {
    extern __shared__ char smem[];
    const uint32_t sb = smem_u32(smem);
    const int tid = threadIdx.x;
    const int wid = tid >> 5, lane = tid & 31;
    const int wm = wid >> 3, wn = wid & 7;        // 2 x 8 warp grid
    const int bz = blockIdx.z;
    A += (size_t)bz * sA;
    B += (size_t)bz * sB;
    const size_t cOff = (size_t)bz * sC;
    const int m0 = blockIdx.y * 128;
    const int n0 = blockIdx.x * 256;

    float acc[4][4][4];
#pragma unroll
    for (int i = 0; i < 4; i++)
#pragma unroll
        for (int j = 0; j < 4; j++)
#pragma unroll
            for (int r = 0; r < 4; r++) acc[i][j][r] = 0.f;

    const int nch = K / 32;

    // ---- prologue: stages 0..NST-2 ----
#pragma unroll
    for (int s = 0; s < NST - 1; s++) {
        const uint32_t stg = sb + s * STAGE;
        const int k0 = s * 32;
        {   // A: 128 rows x 4 chunks = 512 cp.async (one per thread)
            int row = tid >> 2, u = tid & 3;
            cpa16(stg + T_A + row * ROWB + u * 16,
                  A + (size_t)(m0 + row) * lda + k0 + u * 8);
        }
#pragma unroll
        for (int i = 0; i < 2; i++) {   // B: 256 rows x 4 chunks = 1024
            int idx = tid + i * NTHR;
            int row = idx >> 2, u = idx & 3;
            cpa16(stg + T_B + row * ROWB + u * 16,
                  B + (size_t)(n0 + row) * ldb + k0 + u * 8);
        }
        CP_COMMIT();
    }

    const int lr = lane & 15, lc = lane >> 4;                 // A frag addr
    const int nr = ((lane >> 4) << 3) | (lane & 7);           // B frag addr
    const int kc = (lane >> 3) & 1;

    for (int c = 0; c < nch; c++) {
        CP_WAIT(NST - 2);
        __syncthreads();
        // issue loads for stage c + NST - 1
        if (c + NST - 1 < nch) {
            const uint32_t stg = sb + ((c + NST - 1) % NST) * STAGE;
            const int k0 = (c + NST - 1) * 32;
            {
                int row = tid >> 2, u = tid & 3;
                cpa16(stg + T_A + row * ROWB + u * 16,
                      A + (size_t)(m0 + row) * lda + k0 + u * 8);
            }
#pragma unroll
            for (int i = 0; i < 2; i++) {
                int idx = tid + i * NTHR;
                int row = idx >> 2, u = idx & 3;
                cpa16(stg + T_B + row * ROWB + u * 16,
                      B + (size_t)(n0 + row) * ldb + k0 + u * 8);
            }
        }
        CP_COMMIT();

        const uint32_t stg = sb + (c % NST) * STAGE;
#pragma unroll
        for (int kk = 0; kk < 2; kk++) {
            uint32_t af[4][4], bf[2][4];
#pragma unroll
            for (int mi = 0; mi < 4; mi++) {
                uint32_t a = stg + T_A + (uint32_t)(wm * 64 + mi * 16 + lr) * ROWB
                           + lc * 16 + kk * 32;
                LDSM4(af[mi], a);
            }
#pragma unroll
            for (int nt = 0; nt < 2; nt++) {
                uint32_t b = stg + T_B + (uint32_t)(wn * 32 + nt * 16 + nr) * ROWB
                           + kc * 16 + kk * 32;
                LDSM4(bf[nt], b);
            }
#pragma unroll
            for (int mi = 0; mi < 4; mi++)
#pragma unroll
                for (int nt = 0; nt < 2; nt++) {
                    MMA_F16(acc[mi][2 * nt + 0], af[mi], bf[nt]);
                    MMA_F16(acc[mi][2 * nt + 1], af[mi], (bf[nt] + 2));
                }
        }
    }

    // ---- epilogue ----
    const int r = lane >> 2;
    const int cb = 2 * (lane & 3);
#pragma unroll
    for (int mi = 0; mi < 4; mi++) {
#pragma unroll
        for (int h = 0; h < 2; h++) {
            const int m = m0 + wm * 64 + mi * 16 + h * 8 + r;
            const float bm = (bias_mode == 1) ? bias[m] : 0.f;
#pragma unroll
            for (int ni = 0; ni < 4; ni++) {
                const int n = n0 + wn * 32 + ni * 8 + cb;
                float v0 = acc[mi][ni][h * 2 + 0] * alpha + bm;
                float v1 = acc[mi][ni][h * 2 + 1] * alpha + bm;
                if (bias_mode == 2) { v0 += bias[n]; v1 += bias[n + 1]; }
                const size_t off = cOff + (size_t)m * ldc + n;
                if (Cf) {
                    if (resid) { v0 += resid[off]; v1 += resid[off + 1]; }
                    float2 o; o.x = v0; o.y = v1;
                    *(float2*)(Cf + off) = o;
                } else {
                    __half2 p;
                    p.x = __float2half(v0);
                    p.y = __float2half(v1);
                    *(__half2*)(Ch + off) = p;
                }
            }
        }
    }
}

// ---------------- launch -----------------------------------------------------
extern "C" void kernel_launch(void* const* d_in, const int* in_sizes, int n_in,
                              void* d_out, int out_size) {
    const float* x     = (const float*)d_in[0];
    const float* gamma = (const float*)d_in[1];
    const float* beta  = (const float*)d_in[2];
    const float* wq    = (const float*)d_in[3];
    const float* bq    = (const float*)d_in[4];
    const float* wk    = (const float*)d_in[5];
    const float* bk    = (const float*)d_in[6];
    const float* wv    = (const float*)d_in[7];
    const float* bv    = (const float*)d_in[8];
    const float* wo    = (const float*)d_in[9];
    const float* bo    = (const float*)d_in[10];
    float* out = (float*)d_out;

    cudaFuncSetAttribute(gemm_f16, cudaFuncAttributeMaxDynamicSharedMemorySize,
                         SMEM_GEMM);

    __half *hT, *w, *qT, *kT, *v, *attn, *oT;
    float* S;
    cudaGetSymbolAddress((void**)&hT, g_hT);
    cudaGetSymbolAddress((void**)&w, g_w);
    cudaGetSymbolAddress((void**)&qT, g_qT);
    cudaGetSymbolAddress((void**)&kT, g_kT);
    cudaGetSymbolAddress((void**)&v, g_v);
    cudaGetSymbolAddress((void**)&S, g_S);
    cudaGetSymbolAddress((void**)&attn, g_attn);
    cudaGetSymbolAddress((void**)&oT, g_oT);

    const float scale = 0.044194173824159216f;   // 512^-0.5
    const int WN = NCH * NCH;                    // 262144

    // 1) GroupNorm stats + normalize/transpose/convert
    gn_stats_kernel<<<NB * NGROUPS, 256>>>(x);
    gn_tr_kernel<<<dim3(NSP / 32, NCH / 32, NB), dim3(32, 8)>>>(x, gamma, beta);

    // 2) weight converts (one launch)
    cvt4_kernel<<<WN / 256, 256>>>(wq, wk, wv, wo, w);

    // 3) qT[n,co] = hT[n,ci] . wq[co,ci]^T + bq   (M=4096, N=512, K=512)
    gemm_f16<<<dim3(NCH / 256, NSP / 128, NB), NTHR, SMEM_GEMM>>>(
        hT, (long long)BCH_N, NCH, w + 0 * WN, 0, NCH,
        nullptr, qT, (long long)BCH_N, NCH, bq, 2, nullptr, 1.f, NCH);
    gemm_f16<<<dim3(NCH / 256, NSP / 128, NB), NTHR, SMEM_GEMM>>>(
        hT, (long long)BCH_N, NCH, w + 1 * WN, 0, NCH,
        nullptr, kT, (long long)BCH_N, NCH, bk, 2, nullptr, 1.f, NCH);
    // v[c,n] = wv[c,ci] . hT[n,ci]^T + bv        (M=512, N=4096, K=512)
    gemm_f16<<<dim3(NSP / 256, NCH / 128, NB), NTHR, SMEM_GEMM>>>(
        w + 2 * WN, 0, NCH, hT, (long long)BCH_N, NCH,
        nullptr, v, (long long)BCH_N, NSP, bv, 1, nullptr, 1.f, NCH);

    // 4) S[i,j] = scale * qT[i,c] . kT[j,c]^T    (M=4096, N=4096, K=512)
    gemm_f16<<<dim3(NSP / 256, NSP / 128, NB), NTHR, SMEM_GEMM>>>(
        qT, (long long)BCH_N, NCH, kT, (long long)BCH_N, NCH,
        S, nullptr, (long long)ATT_N, NSP, nullptr, 0, nullptr, scale, NCH);

    // 5) softmax rows -> attn fp16
    softmax_kernel<<<NB * NSP, 256>>>(S);

    // 6) oT[i,c] = attn[i,j] . v[c,j]^T          (M=4096, N=512, K=4096)
    gemm_f16<<<dim3(NCH / 256, NSP / 128, NB), NTHR, SMEM_GEMM>>>(
        attn, (long long)ATT_N, NSP, v, (long long)BCH_N, NSP,
        nullptr, oT, (long long)BCH_N, NCH, nullptr, 0, nullptr, 1.f, NSP);

    // 7) out[c,n] = wo[c,ci] . oT[n,ci]^T + bo + x  (M=512, N=4096, K=512)
    gemm_f16<<<dim3(NSP / 256, NCH / 128, NB), NTHR, SMEM_GEMM>>>(
        w + 3 * WN, 0, NCH, oT, (long long)BCH_N, NCH,
        out, nullptr, (long long)BCH_N, NSP, bo, 1, x, 1.f, NCH);
}

// round 14
// speedup vs baseline: 5.7404x; 1.0359x over previous
#include <cuda_runtime.h>
#include <cuda_fp16.h>
#include <math.h>
#include <stdint.h>

#define NB 2
#define NCH 512
#define NSP 4096
#define NGROUPS 32
#define GELEMS 65536                       // 16 * 4096 per (b,g)
#define BCH_N ((size_t)NCH * NSP)          // 2097152
#define QK_N  ((size_t)NSP * 1024)         // qkT per-batch stride
#define ATT_N ((size_t)NSP * NSP)          // 16777216

// ---------------- scratch (static device globals; no allocations) ------------
__device__ __half g_hT[NB * NSP * NCH];        // [b][n][c]
__device__ __half g_w[4][NCH * NCH];           // wq, wk, wv, wo (wq,wk adjacent!)
__device__ float  g_bqk[1024];                 // concat(bq, bk)
__device__ __half g_qkT[NB * NSP * 1024];      // [b][n][q:0..511 | k:512..1023]
__device__ __half g_v[NB * NCH * NSP];         // [b][c][n]
__device__ float  g_S[(size_t)NB * NSP * NSP];        // 134 MB
__device__ __half g_attn[(size_t)NB * NSP * NSP];     // [b][i][j]
__device__ __half g_oT[NB * NSP * NCH];        // [b][i][c]
__device__ float  g_stats[NB * NGROUPS * 2];

// ---------------- PTX helpers ------------------------------------------------
__device__ __forceinline__ uint32_t smem_u32(const void* p) {
    uint32_t a;
    asm("{ .reg .u64 t; cvta.to.shared.u64 t, %1; cvt.u32.u64 %0, t; }" : "=r"(a) : "l"(p));
    return a;
}
__device__ __forceinline__ void cpa16(uint32_t dst, const void* src) {
    asm volatile("cp.async.cg.shared.global [%0], [%1], 16;" :: "r"(dst), "l"(src));
}
#define CP_COMMIT() asm volatile("cp.async.commit_group;")
#define CP_WAIT(n)  asm volatile("cp.async.wait_group %0;" :: "n"(n) : "memory")

#define LDSM4(r, a) \
    asm volatile("ldmatrix.sync.aligned.m8n8.x4.shared.b16 {%0,%1,%2,%3}, [%4];" \
        : "=r"((r)[0]), "=r"((r)[1]), "=r"((r)[2]), "=r"((r)[3]) : "r"(a))
#define MMA_F16(d, a, b) \
    asm volatile("mma.sync.aligned.m16n8k16.row.col.f32.f16.f16.f32 " \
        "{%0,%1,%2,%3}, {%4,%5,%6,%7}, {%8,%9}, {%0,%1,%2,%3};" \
        : "+f"((d)[0]), "+f"((d)[1]), "+f"((d)[2]), "+f"((d)[3]) \
        : "r"((a)[0]), "r"((a)[1]), "r"((a)[2]), "r"((a)[3]), \
          "r"((b)[0]), "r"((b)[1]))

// ---------------- GroupNorm stats --------------------------------------------
__global__ void gn_stats_kernel(const float* __restrict__ x) {
    __shared__ float sh_s[256], sh_ss[256];
    const int bg = blockIdx.x;
    const float* p = x + (size_t)bg * GELEMS;
    float s = 0.f, ss = 0.f;
    for (int i = threadIdx.x * 4; i < GELEMS; i += 256 * 4) {
        float4 v = *(const float4*)&p[i];
        s  += v.x + v.y + v.z + v.w;
        ss += v.x * v.x + v.y * v.y + v.z * v.z + v.w * v.w;
    }
    sh_s[threadIdx.x] = s; sh_ss[threadIdx.x] = ss;
    __syncthreads();
    for (int st = 128; st > 0; st >>= 1) {
        if (threadIdx.x < st) {
            sh_s[threadIdx.x]  += sh_s[threadIdx.x + st];
            sh_ss[threadIdx.x] += sh_ss[threadIdx.x + st];
        }
        __syncthreads();
    }
    if (threadIdx.x == 0) {
        float mean = sh_s[0] * (1.f / GELEMS);
        float var  = sh_ss[0] * (1.f / GELEMS) - mean * mean;
        g_stats[bg * 2 + 0] = mean;
        g_stats[bg * 2 + 1] = rsqrtf(var + 1e-6f);
    }
}

// ------------- GroupNorm + transpose + fp16 convert --------------------------
__global__ void gn_tr_kernel(const float* __restrict__ x,
                             const float* __restrict__ gamma,
                             const float* __restrict__ beta) {
    __shared__ float t[32][33];
    const int b  = blockIdx.z;
    const int c0 = blockIdx.y * 32;
    const int n0 = blockIdx.x * 32;
    const float* xb = x + (size_t)b * BCH_N;
    const int tx = threadIdx.x, ty = threadIdx.y;
#pragma unroll
    for (int r = 0; r < 4; r++) {
        int c = c0 + ty + r * 8;
        int bg = b * NGROUPS + (c >> 4);
        float mean = g_stats[bg * 2 + 0], rstd = g_stats[bg * 2 + 1];
        float ga = gamma[c] * rstd;
        float be = beta[c] - mean * ga;
        t[ty + r * 8][tx] = xb[(size_t)c * NSP + n0 + tx] * ga + be;
    }
    __syncthreads();
#pragma unroll
    for (int r = 0; r < 4; r++) {
        int n = n0 + ty + r * 8;
        int c = c0 + tx;
        g_hT[((size_t)b * NSP + n) * NCH + c] = __float2half(t[tx][ty + r * 8]);
    }
}

// -------- fp32 -> fp16 convert, all 4 weights + qk bias concat ---------------
__global__ void cvt4_kernel(const float* __restrict__ a, const float* __restrict__ b,
                            const float* __restrict__ c, const float* __restrict__ d,
                            const float* __restrict__ bq, const float* __restrict__ bk,
                            __half* __restrict__ dst) {
    const int WN = NCH * NCH;
    int i = blockIdx.x * blockDim.x + threadIdx.x;
    dst[0 * WN + i] = __float2half(a[i]);
    dst[1 * WN + i] = __float2half(b[i]);
    dst[2 * WN + i] = __float2half(c[i]);
    dst[3 * WN + i] = __float2half(d[i]);
    if (i < NCH) {
        g_bqk[i] = bq[i];
        g_bqk[NCH + i] = bk[i];
    }
}

// ---------------- softmax row -> fp16 ----------------------------------------
__global__ void softmax_kernel(const float* __restrict__ S) {
    __shared__ float row[NSP];
    __shared__ float red[256];
    const size_t r = blockIdx.x;
    const float* p = S + r * NSP;
    const int tid = threadIdx.x;

    float m = -1e30f;
    for (int i = tid; i < NSP; i += 256) {
        float v = p[i];
        row[i] = v;
        m = fmaxf(m, v);
    }
    red[tid] = m; __syncthreads();
    for (int st = 128; st > 0; st >>= 1) {
        if (tid < st) red[tid] = fmaxf(red[tid], red[tid + st]);
        __syncthreads();
    }
    m = red[0]; __syncthreads();

    float s = 0.f;
    for (int i = tid; i < NSP; i += 256) {
        float e = __expf(row[i] - m);
        row[i] = e;
        s += e;
    }
    red[tid] = s; __syncthreads();
    for (int st = 128; st > 0; st >>= 1) {
        if (tid < st) red[tid] += red[tid + st];
        __syncthreads();
    }
    float inv = 1.f / red[0];
    size_t base = r * NSP;
    for (int i = tid; i < NSP; i += 256)
        g_attn[base + i] = __float2half(row[i] * inv);
}

// ---------------- fp16 GEMM via mma.sync (HMMA) ------------------------------
// C[M,N] = alpha * A[M,K] . B[N,K]^T  (+ bias) (+ resid)
// CTA tile 128x128x32, 8 warps (2x4), warp tile 64x32, 4-stage cp.async.
// 2 CTAs / SM (independent barrier domains).
// SMEM rows padded to 80B (64B data + 16B) -> conflict-free ldmatrix.
#define ROWB 80
#define T_A 0
#define T_B 10240
#define STAGE 20480
#define NST 4
#define SMEM_GEMM (NST * STAGE)     // 81920
#define NTHR 256

__global__ void __launch_bounds__(NTHR, 2)
gemm_f16(const __half* __restrict__ A, long long sA, int lda,
         const __half* __restrict__ B, long long sB, int ldb,
         float* __restrict__ Cf, __half* __restrict__ Ch,
         long long sC, int ldc,
         const float* __restrict__ bias, int bias_mode,
         const float* __restrict__ resid, float alpha, int K) {
    extern __shared__ char smem[];
    const uint32_t sb = smem_u32(smem);
    const int tid = threadIdx.x;
    const int wid = tid >> 5, lane = tid & 31;
    const int wm = wid >> 2, wn = wid & 3;        // 2 x 4 warp grid
    const int bz = blockIdx.z;
    A += (size_t)bz * sA;
    B += (size_t)bz * sB;
    const size_t cOff = (size_t)bz * sC;
    const int m0 = blockIdx.y * 128;
    const int n0 = blockIdx.x * 128;

    float acc[4][4][4];
#pragma unroll
    for (int i = 0; i < 4; i++)
#pragma unroll
        for (int j = 0; j < 4; j++)
#pragma unroll
            for (int r = 0; r < 4; r++) acc[i][j][r] = 0.f;

    const int nch = K / 32;

    // ---- prologue: stages 0..NST-2 ----
#pragma unroll
    for (int s = 0; s < NST - 1; s++) {
        const uint32_t stg = sb + s * STAGE;
        const int k0 = s * 32;
#pragma unroll
        for (int i = 0; i < 2; i++) {   // A: 128 rows x 4 chunks = 512
            int idx = tid + i * NTHR;
            int row = idx >> 2, u = idx & 3;
            cpa16(stg + T_A + row * ROWB + u * 16,
                  A + (size_t)(m0 + row) * lda + k0 + u * 8);
        }
#pragma unroll
        for (int i = 0; i < 2; i++) {   // B: 128 rows x 4 chunks = 512
            int idx = tid + i * NTHR;
            int row = idx >> 2, u = idx & 3;
            cpa16(stg + T_B + row * ROWB + u * 16,
                  B + (size_t)(n0 + row) * ldb + k0 + u * 8);
        }
        CP_COMMIT();
    }

    const int lr = lane & 15, lc = lane >> 4;                 // A frag addr
    const int nr = ((lane >> 4) << 3) | (lane & 7);           // B frag addr
    const int kc = (lane >> 3) & 1;

    for (int c = 0; c < nch; c++) {
        CP_WAIT(NST - 2);
        __syncthreads();
        // issue loads for stage c + NST - 1
        if (c + NST - 1 < nch) {
            const uint32_t stg = sb + ((c + NST - 1) % NST) * STAGE;
            const int k0 = (c + NST - 1) * 32;
#pragma unroll
            for (int i = 0; i < 2; i++) {
                int idx = tid + i * NTHR;
                int row = idx >> 2, u = idx & 3;
                cpa16(stg + T_A + row * ROWB + u * 16,
                      A + (size_t)(m0 + row) * lda + k0 + u * 8);
            }
#pragma unroll
            for (int i = 0; i < 2; i++) {
                int idx = tid + i * NTHR;
                int row = idx >> 2, u = idx & 3;
                cpa16(stg + T_B + row * ROWB + u * 16,
                      B + (size_t)(n0 + row) * ldb + k0 + u * 8);
            }
        }
        CP_COMMIT();

        const uint32_t stg = sb + (c % NST) * STAGE;
#pragma unroll
        for (int kk = 0; kk < 2; kk++) {
            uint32_t af[4][4], bf[2][4];
#pragma unroll
            for (int mi = 0; mi < 4; mi++) {
                uint32_t a = stg + T_A + (uint32_t)(wm * 64 + mi * 16 + lr) * ROWB
                           + lc * 16 + kk * 32;
                LDSM4(af[mi], a);
            }
#pragma unroll
            for (int nt = 0; nt < 2; nt++) {
                uint32_t b = stg + T_B + (uint32_t)(wn * 32 + nt * 16 + nr) * ROWB
                           + kc * 16 + kk * 32;
                LDSM4(bf[nt], b);
            }
#pragma unroll
            for (int mi = 0; mi < 4; mi++)
#pragma unroll
                for (int nt = 0; nt < 2; nt++) {
                    MMA_F16(acc[mi][2 * nt + 0], af[mi], bf[nt]);
                    MMA_F16(acc[mi][2 * nt + 1], af[mi], (bf[nt] + 2));
                }
        }
    }

    // ---- epilogue ----
    const int r = lane >> 2;
    const int cb = 2 * (lane & 3);
#pragma unroll
    for (int mi = 0; mi < 4; mi++) {
#pragma unroll
        for (int h = 0; h < 2; h++) {
            const int m = m0 + wm * 64 + mi * 16 + h * 8 + r;
            const float bm = (bias_mode == 1) ? bias[m] : 0.f;
#pragma unroll
            for (int ni = 0; ni < 4; ni++) {
                const int n = n0 + wn * 32 + ni * 8 + cb;
                float v0 = acc[mi][ni][h * 2 + 0] * alpha + bm;
                float v1 = acc[mi][ni][h * 2 + 1] * alpha + bm;
                if (bias_mode == 2) { v0 += bias[n]; v1 += bias[n + 1]; }
                const size_t off = cOff + (size_t)m * ldc + n;
                if (Cf) {
                    if (resid) { v0 += resid[off]; v1 += resid[off + 1]; }
                    float2 o; o.x = v0; o.y = v1;
                    *(float2*)(Cf + off) = o;
                } else {
                    __half2 p;
                    p.x = __float2half(v0);
                    p.y = __float2half(v1);
                    *(__half2*)(Ch + off) = p;
                }
            }
        }
    }
}

// ---------------- launch -----------------------------------------------------
extern "C" void kernel_launch(void* const* d_in, const int* in_sizes, int n_in,
                              void* d_out, int out_size) {
    const float* x     = (const float*)d_in[0];
    const float* gamma = (const float*)d_in[1];
    const float* beta  = (const float*)d_in[2];
    const float* wq    = (const float*)d_in[3];
    const float* bq    = (const float*)d_in[4];
    const float* wk    = (const float*)d_in[5];
    const float* bk    = (const float*)d_in[6];
    const float* wv    = (const float*)d_in[7];
    const float* bv    = (const float*)d_in[8];
    const float* wo    = (const float*)d_in[9];
    const float* bo    = (const float*)d_in[10];
    float* out = (float*)d_out;

    cudaFuncSetAttribute(gemm_f16, cudaFuncAttributeMaxDynamicSharedMemorySize,
                         SMEM_GEMM);

    __half *hT, *w, *qkT, *v, *attn, *oT;
    float *S, *bqk;
    cudaGetSymbolAddress((void**)&hT, g_hT);
    cudaGetSymbolAddress((void**)&w, g_w);
    cudaGetSymbolAddress((void**)&bqk, g_bqk);
    cudaGetSymbolAddress((void**)&qkT, g_qkT);
    cudaGetSymbolAddress((void**)&v, g_v);
    cudaGetSymbolAddress((void**)&S, g_S);
    cudaGetSymbolAddress((void**)&attn, g_attn);
    cudaGetSymbolAddress((void**)&oT, g_oT);

    const float scale = 0.044194173824159216f;   // 512^-0.5
    const int WN = NCH * NCH;                    // 262144

    // 1) GroupNorm stats + normalize/transpose/convert
    gn_stats_kernel<<<NB * NGROUPS, 256>>>(x);
    gn_tr_kernel<<<dim3(NSP / 32, NCH / 32, NB), dim3(32, 8)>>>(x, gamma, beta);

    // 2) weight converts (one launch) + qk bias concat
    cvt4_kernel<<<WN / 256, 256>>>(wq, wk, wv, wo, bq, bk, w);

    // 3) fused qk proj: qkT[n, 0:1024] = hT[n,ci] . [wq;wk][co,ci]^T + bqk
    //    (M=4096, N=1024, K=512)
    gemm_f16<<<dim3(1024 / 128, NSP / 128, NB), NTHR, SMEM_GEMM>>>(
        hT, (long long)BCH_N, NCH, w, 0, NCH,
        nullptr, qkT, (long long)QK_N, 1024, bqk, 2, nullptr, 1.f, NCH);
    // v[c,n] = wv[c,ci] . hT[n,ci]^T + bv        (M=512, N=4096, K=512)
    gemm_f16<<<dim3(NSP / 128, NCH / 128, NB), NTHR, SMEM_GEMM>>>(
        w + 2 * WN, 0, NCH, hT, (long long)BCH_N, NCH,
        nullptr, v, (long long)BCH_N, NSP, bv, 1, nullptr, 1.f, NCH);

    // 4) S[i,j] = scale * q[i,c] . k[j,c]^T      (M=4096, N=4096, K=512)
    gemm_f16<<<dim3(NSP / 128, NSP / 128, NB), NTHR, SMEM_GEMM>>>(
        qkT, (long long)QK_N, 1024, qkT + NCH, (long long)QK_N, 1024,
        S, nullptr, (long long)ATT_N, NSP, nullptr, 0, nullptr, scale, NCH);

    // 5) softmax rows -> attn fp16
    softmax_kernel<<<NB * NSP, 256>>>(S);

    // 6) oT[i,c] = attn[i,j] . v[c,j]^T          (M=4096, N=512, K=4096)
    gemm_f16<<<dim3(NCH / 128, NSP / 128, NB), NTHR, SMEM_GEMM>>>(
        attn, (long long)ATT_N, NSP, v, (long long)BCH_N, NSP,
        nullptr, oT, (long long)BCH_N, NCH, nullptr, 0, nullptr, 1.f, NSP);

    // 7) out[c,n] = wo[c,ci] . oT[n,ci]^T + bo + x  (M=512, N=4096, K=512)
    gemm_f16<<<dim3(NSP / 128, NCH / 128, NB), NTHR, SMEM_GEMM>>>(
        w + 3 * WN, 0, NCH, oT, (long long)BCH_N, NCH,
        out, nullptr, (long long)BCH_N, NSP, bo, 1, x, 1.f, NCH);
}